// round 12
// baseline (speedup 1.0000x reference)
#include <cuda_runtime.h>
#include <cuda_fp16.h>
#include <math.h>
#include <stdint.h>

#define N_TOK 2048
#define DIMX  1024
#define HEADS 16
#define DHEAD 64
#define INNER 1024
#define NQKV  3072
#define ALPHA_C 0.45f
#define SCALE_C 0.125f

typedef __half fp16;

// ---------------- device buffers ----------------
__device__ __align__(256) float g_c12[(size_t)N_TOK * NQKV];
__device__ __align__(256) fp16  g_xnh[(size_t)N_TOK * DIMX];
__device__ __align__(256) fp16  g_xnl[(size_t)N_TOK * DIMX];
__device__ __align__(256) fp16  g_wqkv[(size_t)NQKV * DIMX];
__device__ __align__(256) fp16  g_wo[(size_t)DIMX * INNER];
__device__ __align__(256) fp16  g_qh[(size_t)HEADS * N_TOK * DHEAD];
__device__ __align__(256) fp16  g_ql[(size_t)HEADS * N_TOK * DHEAD];
__device__ __align__(256) fp16  g_k[(size_t)HEADS * N_TOK * DHEAD];
__device__ __align__(256) fp16  g_vt[(size_t)HEADS * DHEAD * N_TOK];
__device__ __align__(256) fp16  g_at[(size_t)HEADS * N_TOK * N_TOK];  // [i][g][j]
__device__ __align__(256) fp16  g_ao[(size_t)N_TOK * INNER];

// ---------------- helpers ----------------
__device__ __forceinline__ uint32_t s2u(const void* p) {
    return (uint32_t)__cvta_generic_to_shared(p);
}
__device__ __forceinline__ void cp16(uint32_t d, const void* g) {
    asm volatile("cp.async.cg.shared.global [%0],[%1],16;" :: "r"(d), "l"(g));
}
__device__ __forceinline__ void cpcommit() { asm volatile("cp.async.commit_group;"); }
template<int Nw> __device__ __forceinline__ void cpwait() {
    asm volatile("cp.async.wait_group %0;" :: "n"(Nw));
}
__device__ __forceinline__ void ldsm4(uint32_t* r, uint32_t addr) {
    asm volatile("ldmatrix.sync.aligned.m8n8.x4.shared.b16 {%0,%1,%2,%3},[%4];"
                 : "=r"(r[0]), "=r"(r[1]), "=r"(r[2]), "=r"(r[3]) : "r"(addr));
}
__device__ __forceinline__ void mma_f16(float* d, const uint32_t* a, uint32_t b0, uint32_t b1) {
    asm volatile(
        "mma.sync.aligned.m16n8k16.row.col.f32.f16.f16.f32 "
        "{%0,%1,%2,%3},{%4,%5,%6,%7},{%8,%9},{%0,%1,%2,%3};"
        : "+f"(d[0]), "+f"(d[1]), "+f"(d[2]), "+f"(d[3])
        : "r"(a[0]), "r"(a[1]), "r"(a[2]), "r"(a[3]), "r"(b0), "r"(b1));
}
__device__ __forceinline__ void split2h(float v, fp16& h, fp16& l) {
    h = __float2half_rn(v);
    l = __float2half_rn(v - __half2float(h));
}
// f32x2 packed helpers
__device__ __forceinline__ unsigned long long dup2(float v) {
    unsigned long long r;
    asm("mov.b64 %0, {%1, %1};" : "=l"(r) : "f"(v));
    return r;
}
__device__ __forceinline__ unsigned long long pack2(float x, float y) {
    unsigned long long r;
    asm("mov.b64 %0, {%1, %2};" : "=l"(r) : "f"(x), "f"(y));
    return r;
}
__device__ __forceinline__ void ffma2(unsigned long long& d,
                                      unsigned long long a, unsigned long long b) {
    asm("fma.rn.f32x2 %0, %1, %2, %3;" : "=l"(d) : "l"(a), "l"(b), "l"(d));
}
__device__ __forceinline__ void unpack2(unsigned long long p, float& x, float& y) {
    asm("mov.b64 {%0, %1}, %2;" : "=f"(x), "=f"(y) : "l"(p));
}

// ---------------- layernorm + fp16 hi/lo split ----------------
__global__ void ln_split_kernel(const float* __restrict__ x,
                                const float* __restrict__ gam,
                                const float* __restrict__ bet,
                                fp16* __restrict__ oh, fp16* __restrict__ ol)
{
    int row = blockIdx.x;
    const float* xr = x + (size_t)row * DIMX;
    float s = 0.f, s2 = 0.f;
    for (int c = threadIdx.x; c < DIMX; c += blockDim.x) {
        float v = xr[c];
        s += v; s2 += v * v;
    }
    __shared__ float red[64];
    for (int o = 16; o > 0; o >>= 1) {
        s  += __shfl_xor_sync(0xffffffffu, s,  o);
        s2 += __shfl_xor_sync(0xffffffffu, s2, o);
    }
    int warp = threadIdx.x >> 5, lane = threadIdx.x & 31;
    int nwarp = blockDim.x >> 5;
    if (lane == 0) { red[warp] = s; red[warp + 32] = s2; }
    __syncthreads();
    if (warp == 0) {
        s  = (lane < nwarp) ? red[lane] : 0.f;
        s2 = (lane < nwarp) ? red[lane + 32] : 0.f;
        for (int o = 16; o > 0; o >>= 1) {
            s  += __shfl_xor_sync(0xffffffffu, s,  o);
            s2 += __shfl_xor_sync(0xffffffffu, s2, o);
        }
        if (lane == 0) { red[0] = s; red[1] = s2; }
    }
    __syncthreads();
    float mean = red[0] * (1.f / DIMX);
    float var  = red[1] * (1.f / DIMX) - mean * mean;
    float inv  = rsqrtf(var + 1e-5f);
    for (int c = threadIdx.x; c < DIMX; c += blockDim.x) {
        float y = (xr[c] - mean) * inv * gam[c] + bet[c];
        fp16 h, l; split2h(y, h, l);
        oh[(size_t)row * DIMX + c] = h;
        ol[(size_t)row * DIMX + c] = l;
    }
}

// ---------------- transpose to single fp16 ----------------
__global__ void tsingle_kernel(const float* __restrict__ in, int ldin, long long sIn,
                               fp16* __restrict__ o, int ldout, long long sOut,
                               int R, int C)
{
    __shared__ float t[32][33];
    in += (size_t)blockIdx.z * sIn;
    o  += (size_t)blockIdx.z * sOut;
    int r0 = blockIdx.y * 32, c0 = blockIdx.x * 32;
    int tx = threadIdx.x & 31, ty = threadIdx.x >> 5;
#pragma unroll
    for (int i = 0; i < 32; i += 8) {
        int r = r0 + ty + i;
        if (r < R && c0 + tx < C) t[ty + i][tx] = in[(size_t)r * ldin + c0 + tx];
    }
    __syncthreads();
#pragma unroll
    for (int i = 0; i < 32; i += 8) {
        int c = c0 + ty + i, r = r0 + tx;
        if (c < C && r < R)
            o[(size_t)c * ldout + r] = __float2half_rn(t[tx][ty + i]);
    }
}

// ---------------- remap: q -> hi/lo split, k -> single ----------------
__global__ void remap_split(const float* __restrict__ c12,
                            fp16* __restrict__ qh, fp16* __restrict__ ql,
                            fp16* __restrict__ k)
{
    int idx = blockIdx.x * blockDim.x + threadIdx.x;
    if (idx >= N_TOK * INNER) return;
    int i = idx >> 10, col = idx & 1023;
    int h = col >> 6, d = col & 63;
    float qv = c12[(size_t)i * NQKV + col];
    float kv = c12[(size_t)i * NQKV + INNER + col];
    size_t dst = ((size_t)h * N_TOK + i) * DHEAD + d;
    fp16 a, b;
    split2h(qv, a, b); qh[dst] = a; ql[dst] = b;
    k[dst] = __float2half_rn(kv);
}

// ---------------- fp16 tensor-core GEMM ----------------
// C = alpha * A @ B^T.  128 threads, warp grid (BM/WM) x (BN/WN) = 4 warps.
// ASPLIT: A hi/lo (adds al*b MMA).
// MODE 0: C fp32 (+bias). MODE 1: C single fp16. MODE 2: blend with Hm -> fp32.
template<int BM, int BN, int WM, int WN, int ASPLIT, int MODE>
__global__ void __launch_bounds__(128, 2)
gemm_f16(const fp16* __restrict__ Ahi, const fp16* __restrict__ Alo,
         const fp16* __restrict__ Bhi,
         float* __restrict__ C, fp16* __restrict__ Ch,
         const float* __restrict__ Hm,
         int K, int lda, int ldb, int ldc,
         long long sA, long long sB, long long sC,
         float alpha, const float* __restrict__ bias)
{
    constexpr int MI  = WM / 16;
    constexpr int NJ  = WN / 16;
    constexpr int NJ2 = WN / 8;
    constexpr int NAI = BM / 16;
    constexpr int NBI = BN / 16;
    constexpr int ABUF = (ASPLIT ? 2 : 1) * BM * 64;  // halves
    constexpr int BBUF = BN * 64;
    constexpr int SS   = ABUF + BBUF;
    constexpr int WNN = BN / WN;

    extern __shared__ fp16 sm[];

    Ahi += (size_t)blockIdx.z * sA;
    if (ASPLIT) Alo += (size_t)blockIdx.z * sA;
    Bhi += (size_t)blockIdx.z * sB;
    if (MODE == 1) Ch += (size_t)blockIdx.z * sC;
    else           C  += (size_t)blockIdx.z * sC;
    if (MODE == 2) Hm += (size_t)blockIdx.z * sC;

    const int bm = blockIdx.y * BM, bn = blockIdx.x * BN;
    const int tid = threadIdx.x, lane = tid & 31, wid = tid >> 5;
    const int wm0 = (wid / WNN) * WM, wn0 = (wid % WNN) * WN;

    float acc[MI][NJ2][4];
#pragma unroll
    for (int i = 0; i < MI; i++)
#pragma unroll
        for (int j = 0; j < NJ2; j++) {
            acc[i][j][0] = 0.f; acc[i][j][1] = 0.f;
            acc[i][j][2] = 0.f; acc[i][j][3] = 0.f;
        }

    auto issue = [&](int kt, int stg) {
        fp16* sA_hi = sm + stg * SS;
        fp16* sA_lo = sA_hi + BM * 64;
        fp16* sB_hi = sA_hi + ABUF;
#pragma unroll
        for (int i = 0; i < NAI; i++) {
            int id = tid + i * 128, r = id >> 3, c = id & 7;
            size_t go = (size_t)(bm + r) * lda + kt * 64 + c * 8;
            int so = r * 64 + ((c ^ (r & 7)) << 3);
            cp16(s2u(sA_hi + so), Ahi + go);
            if (ASPLIT) cp16(s2u(sA_lo + so), Alo + go);
        }
#pragma unroll
        for (int i = 0; i < NBI; i++) {
            int id = tid + i * 128, r = id >> 3, c = id & 7;
            size_t go = (size_t)(bn + r) * ldb + kt * 64 + c * 8;
            int so = r * 64 + ((c ^ (r & 7)) << 3);
            cp16(s2u(sB_hi + so), Bhi + go);
        }
    };

    const int KT = K >> 6;
    issue(0, 0); cpcommit();

    for (int kt = 0; kt < KT; kt++) {
        int cur = kt & 1;
        if (kt + 1 < KT) { issue(kt + 1, cur ^ 1); cpcommit(); cpwait<1>(); }
        else             { cpwait<0>(); }
        __syncthreads();

        const fp16* sA_hi = sm + cur * SS;
        const fp16* sA_lo = sA_hi + BM * 64;
        const fp16* sB_hi = sA_hi + ABUF;

#pragma unroll
        for (int s = 0; s < 4; s++) {
            const int c0 = 2 * s;
            uint32_t ah[MI][4], al[MI][4];
#pragma unroll
            for (int mi = 0; mi < MI; mi++) {
                int row = wm0 + mi * 16 + (lane & 15);
                int ch  = c0 + (lane >> 4);
                int off = row * 64 + ((ch ^ (row & 7)) << 3);
                ldsm4(ah[mi], s2u(sA_hi + off));
                if (ASPLIT) ldsm4(al[mi], s2u(sA_lo + off));
            }
#pragma unroll
            for (int nj = 0; nj < NJ; nj++) {
                int rowb = wn0 + nj * 16 + (lane & 15);
                int ch   = c0 + (lane >> 4);
                int off  = rowb * 64 + ((ch ^ (rowb & 7)) << 3);
                uint32_t bb[4];
                ldsm4(bb, s2u(sB_hi + off));
#pragma unroll
                for (int mi = 0; mi < MI; mi++) {
                    mma_f16(acc[mi][2 * nj],     ah[mi], bb[0], bb[2]);
                    mma_f16(acc[mi][2 * nj + 1], ah[mi], bb[1], bb[3]);
                    if (ASPLIT) {
                        mma_f16(acc[mi][2 * nj],     al[mi], bb[0], bb[2]);
                        mma_f16(acc[mi][2 * nj + 1], al[mi], bb[1], bb[3]);
                    }
                }
            }
        }
        __syncthreads();
    }

    // ---- epilogue ----
#pragma unroll
    for (int mi = 0; mi < MI; mi++) {
#pragma unroll
        for (int nj2 = 0; nj2 < NJ2; nj2++) {
            int r0  = bm + wm0 + mi * 16 + (lane >> 2);
            int col = bn + wn0 + nj2 * 8 + (lane & 3) * 2;
            float v0 = acc[mi][nj2][0] * alpha, v1 = acc[mi][nj2][1] * alpha;
            float v2 = acc[mi][nj2][2] * alpha, v3 = acc[mi][nj2][3] * alpha;
            size_t o0 = (size_t)r0 * ldc + col;
            size_t o1 = o0 + (size_t)8 * ldc;
            if (MODE == 1) {
                *(__half2*)&Ch[o0] = __halves2half2(__float2half_rn(v0), __float2half_rn(v1));
                *(__half2*)&Ch[o1] = __halves2half2(__float2half_rn(v2), __float2half_rn(v3));
            } else if (MODE == 2) {
                float2 ha = *(const float2*)&Hm[o0];
                float2 hb = *(const float2*)&Hm[o1];
                *(float2*)&C[o0] = make_float2(ALPHA_C * v0 + (1.f - ALPHA_C) * ha.x,
                                               ALPHA_C * v1 + (1.f - ALPHA_C) * ha.y);
                *(float2*)&C[o1] = make_float2(ALPHA_C * v2 + (1.f - ALPHA_C) * hb.x,
                                               ALPHA_C * v3 + (1.f - ALPHA_C) * hb.y);
            } else {
                if (bias) {
                    float b0 = bias[col], b1 = bias[col + 1];
                    v0 += b0; v1 += b1; v2 += b0; v3 += b1;
                }
                *(float2*)&C[o0] = make_float2(v0, v1);
                *(float2*)&C[o1] = make_float2(v2, v3);
            }
        }
    }
}

// ---------------- fused mix_pre + softmax + mix_post ----------------
// Round-9 structure; mixes use fma.rn.f32x2 with packed weight tables.
__global__ void __launch_bounds__(512)
fused_softmax(const float* __restrict__ blended,
              const float* __restrict__ mpre, const float* __restrict__ mpost,
              fp16* __restrict__ at)
{
    extern __shared__ float sd[];
    __shared__ unsigned long long smixA2[HEADS * HEADS], smixB2[HEADS * HEADS];
    __shared__ float redm[16][HEADS], redl[16][HEADS];
    __shared__ float fm[HEADS], fl[HEADS];

    const int i = blockIdx.x, tid = threadIdx.x;
    if (tid < 256) { smixA2[tid] = dup2(mpre[tid]); smixB2[tid] = dup2(mpost[tid]); }
    __syncthreads();

    const size_t sH = (size_t)N_TOK * N_TOK;
    const size_t hbase = (size_t)i * N_TOK;
    const int j = tid * 4;

    unsigned long long bl01[HEADS], bl23[HEADS];
#pragma unroll
    for (int h = 0; h < HEADS; h++) {
        float4 b = *(const float4*)&blended[(size_t)h * sH + hbase + j];
        bl01[h] = pack2(b.x, b.y);
        bl23[h] = pack2(b.z, b.w);
    }

    float m[HEADS], l[HEADS];
#pragma unroll
    for (int g = 0; g < HEADS; g++) {
        unsigned long long d01 = 0ull, d23 = 0ull;
#pragma unroll
        for (int h = 0; h < HEADS; h++) {
            unsigned long long w2 = smixA2[h * HEADS + g];
            ffma2(d01, bl01[h], w2);
            ffma2(d23, bl23[h], w2);
        }
        float dx, dy, dz, dw;
        unpack2(d01, dx, dy); unpack2(d23, dz, dw);
        *(float4*)&sd[g * N_TOK + j] = make_float4(dx, dy, dz, dw);
        float mx = fmaxf(fmaxf(dx, dy), fmaxf(dz, dw));
        m[g] = mx;
        l[g] = __expf(dx - mx) + __expf(dy - mx)
             + __expf(dz - mx) + __expf(dw - mx);
    }

#pragma unroll
    for (int g = 0; g < HEADS; g++) {
        for (int o = 16; o > 0; o >>= 1) {
            float m2 = __shfl_xor_sync(0xffffffffu, m[g], o);
            float l2 = __shfl_xor_sync(0xffffffffu, l[g], o);
            float nm = fmaxf(m[g], m2);
            l[g] = l[g] * __expf(m[g] - nm) + l2 * __expf(m2 - nm);
            m[g] = nm;
        }
    }
    int warp = tid >> 5, lane = tid & 31;
    if (lane == 0) {
#pragma unroll
        for (int g = 0; g < HEADS; g++) { redm[warp][g] = m[g]; redl[warp][g] = l[g]; }
    }
    __syncthreads();
    if (tid < HEADS) {
        int g = tid;
        float M = redm[0][g], L = redl[0][g];
#pragma unroll
        for (int w = 1; w < 16; w++) {
            float m2 = redm[w][g], l2 = redl[w][g];
            float nm = fmaxf(M, m2);
            L = L * __expf(M - nm) + l2 * __expf(m2 - nm);
            M = nm;
        }
        fm[g] = M; fl[g] = 1.0f / L;
    }
    __syncthreads();

    unsigned long long p01[HEADS], p23[HEADS];
#pragma unroll
    for (int h = 0; h < HEADS; h++) {
        float mh = fm[h], li = fl[h];
        float4 d = *(const float4*)&sd[h * N_TOK + j];
        p01[h] = pack2(__expf(d.x - mh) * li, __expf(d.y - mh) * li);
        p23[h] = pack2(__expf(d.z - mh) * li, __expf(d.w - mh) * li);
    }
    const size_t rbase = (size_t)i * (HEADS * N_TOK);
#pragma unroll
    for (int g = 0; g < HEADS; g++) {
        unsigned long long a01 = 0ull, a23 = 0ull;
#pragma unroll
        for (int h = 0; h < HEADS; h++) {
            unsigned long long w2 = smixB2[h * HEADS + g];
            ffma2(a01, p01[h], w2);
            ffma2(a23, p23[h], w2);
        }
        float ax, ay, az, aw;
        unpack2(a01, ax, ay); unpack2(a23, az, aw);
        size_t o = rbase + g * N_TOK + j;
        ((__half2*)&at[o])[0] = __halves2half2(__float2half_rn(ax), __float2half_rn(ay));
        ((__half2*)&at[o])[1] = __halves2half2(__float2half_rn(az), __float2half_rn(aw));
    }
}

// ---------------- launch ----------------
extern "C" void kernel_launch(void* const* d_in, const int* in_sizes, int n_in,
                              void* d_out, int out_size)
{
    const float* x        = (const float*)d_in[0];
    const float* h_in     = (const float*)d_in[1];
    const float* ln_g     = (const float*)d_in[2];
    const float* ln_b     = (const float*)d_in[3];
    const float* Wq       = (const float*)d_in[4];
    const float* Wkv      = (const float*)d_in[5];
    const float* mix_pre  = (const float*)d_in[6];
    const float* mix_post = (const float*)d_in[7];
    const float* Wout     = (const float*)d_in[8];
    const float* bout     = (const float*)d_in[9];

    float* out = (float*)d_out;
    float* blended_out = out + (size_t)N_TOK * DIMX;

    float* c12;
    fp16 *xnh, *xnl, *wqkv, *wo, *qh, *ql, *k, *vt, *at, *ao;
    cudaGetSymbolAddress((void**)&c12,  g_c12);
    cudaGetSymbolAddress((void**)&xnh,  g_xnh);
    cudaGetSymbolAddress((void**)&xnl,  g_xnl);
    cudaGetSymbolAddress((void**)&wqkv, g_wqkv);
    cudaGetSymbolAddress((void**)&wo,   g_wo);
    cudaGetSymbolAddress((void**)&qh,   g_qh);
    cudaGetSymbolAddress((void**)&ql,   g_ql);
    cudaGetSymbolAddress((void**)&k,    g_k);
    cudaGetSymbolAddress((void**)&vt,   g_vt);
    cudaGetSymbolAddress((void**)&at,   g_at);
    cudaGetSymbolAddress((void**)&ao,   g_ao);

    // smem sizes (bytes)
    const int SM_QKV = 2 * (2 * 128 + 128) * 128;   // 98304 (A split, 2 stg)
    const int SM_QK  = (2 * 128 + 128) * 128;       // 49152 (A split, KT=1, 1 stg)
    const int SM_AV  = 2 * (128 + 64) * 128;        // 49152 (no split, 2 stg)
    const int SM_SOFT = HEADS * N_TOK * 4;          // 131072
    cudaFuncSetAttribute(gemm_f16<128, 128, 64, 64, 1, 0>,
                         cudaFuncAttributeMaxDynamicSharedMemorySize, SM_QKV);
    cudaFuncSetAttribute(gemm_f16<128, 128, 64, 64, 1, 2>,
                         cudaFuncAttributeMaxDynamicSharedMemorySize, SM_QK);
    cudaFuncSetAttribute(gemm_f16<128, 64, 64, 32, 0, 1>,
                         cudaFuncAttributeMaxDynamicSharedMemorySize, SM_AV);
    cudaFuncSetAttribute(gemm_f16<128, 64, 64, 32, 0, 0>,
                         cudaFuncAttributeMaxDynamicSharedMemorySize, SM_AV);
    cudaFuncSetAttribute(fused_softmax,
                         cudaFuncAttributeMaxDynamicSharedMemorySize, SM_SOFT);

    // 1. layernorm + fp16 split
    ln_split_kernel<<<N_TOK, 256>>>(x, ln_g, ln_b, xnh, xnl);

    // 2. weight transposes -> single fp16 K-major
    tsingle_kernel<<<dim3(32, 32, 1), 256>>>(Wq, INNER, 0, wqkv, DIMX, 0, DIMX, INNER);
    tsingle_kernel<<<dim3(64, 32, 1), 256>>>(Wkv, 2 * INNER, 0,
                                             wqkv + (size_t)INNER * DIMX, DIMX, 0,
                                             DIMX, 2 * INNER);
    tsingle_kernel<<<dim3(32, 32, 1), 256>>>(Wout, DIMX, 0, wo, INNER, 0, INNER, DIMX);

    // 3. c12 = xn @ [Wq|Wkv]  (M=2048, N=3072, K=1024)  A-split 2-MMA
    gemm_f16<128, 128, 64, 64, 1, 0><<<dim3(NQKV / 128, N_TOK / 128, 1), 128, SM_QKV>>>(
        xnh, xnl, wqkv, c12, nullptr, nullptr,
        DIMX, DIMX, DIMX, NQKV, 0, 0, 0, 1.f, nullptr);

    // 4. remap q hi/lo, k single; 5. v^T single
    remap_split<<<(N_TOK * INNER + 255) / 256, 256>>>(c12, qh, ql, k);
    tsingle_kernel<<<dim3(2, 64, HEADS), 256>>>(c12 + 2 * INNER, NQKV, DHEAD,
                                                vt, N_TOK, (long long)DHEAD * N_TOK,
                                                N_TOK, DHEAD);

    // 6. blended[h][i][j] = 0.45*SCALE*(q@k^T) + 0.55*h  (A-split 2-MMA)
    gemm_f16<128, 128, 64, 64, 1, 2><<<dim3(N_TOK / 128, N_TOK / 128, HEADS), 128, SM_QK>>>(
        qh, ql, k, blended_out, nullptr, h_in,
        DHEAD, DHEAD, DHEAD, N_TOK,
        (long long)N_TOK * DHEAD, (long long)N_TOK * DHEAD,
        (long long)N_TOK * N_TOK,
        SCALE_C, nullptr);

    // 7. fused mix_pre + softmax + mix_post -> attn single fp16 [i][g][j]
    fused_softmax<<<N_TOK, 512, SM_SOFT>>>(blended_out, mix_pre, mix_post, at);

    // 8. ao = attn @ v  (per head; M=2048, N=64, K=2048) 1-MMA -> single fp16
    gemm_f16<128, 64, 64, 32, 0, 1><<<dim3(1, N_TOK / 128, HEADS), 128, SM_AV>>>(
        at, nullptr, vt, nullptr, ao, nullptr,
        N_TOK, HEADS * N_TOK, N_TOK, INNER,
        (long long)N_TOK, (long long)DHEAD * N_TOK, (long long)DHEAD,
        1.f, nullptr);

    // 9. out = ao @ Wout + bout  (M=2048, N=1024, K=1024) 1-MMA, BN=64 (256 CTAs)
    gemm_f16<128, 64, 64, 32, 0, 0><<<dim3(DIMX / 64, N_TOK / 128, 1), 128, SM_AV>>>(
        ao, nullptr, wo, out, nullptr, nullptr,
        INNER, INNER, INNER, DIMX, 0, 0, 0, 1.f, bout);

    (void)in_sizes; (void)n_in; (void)out_size;
}

// round 13
// speedup vs baseline: 1.0810x; 1.0810x over previous
#include <cuda_runtime.h>
#include <cuda_fp16.h>
#include <math.h>
#include <stdint.h>

#define N_TOK 2048
#define DIMX  1024
#define HEADS 16
#define DHEAD 64
#define INNER 1024
#define NQKV  3072
#define ALPHA_C 0.45f
#define SCALE_C 0.125f

typedef __half fp16;

// ---------------- device buffers ----------------
__device__ __align__(256) float g_c12[(size_t)N_TOK * NQKV];
__device__ __align__(256) fp16  g_xnh[(size_t)N_TOK * DIMX];
__device__ __align__(256) fp16  g_xnl[(size_t)N_TOK * DIMX];
__device__ __align__(256) fp16  g_wqkv[(size_t)NQKV * DIMX];
__device__ __align__(256) fp16  g_wo[(size_t)DIMX * INNER];
__device__ __align__(256) fp16  g_qh[(size_t)HEADS * N_TOK * DHEAD];
__device__ __align__(256) fp16  g_ql[(size_t)HEADS * N_TOK * DHEAD];
__device__ __align__(256) fp16  g_k[(size_t)HEADS * N_TOK * DHEAD];
__device__ __align__(256) fp16  g_vt[(size_t)HEADS * DHEAD * N_TOK];
__device__ __align__(256) fp16  g_at[(size_t)HEADS * N_TOK * N_TOK];  // [i][g][j]
__device__ __align__(256) fp16  g_ao[(size_t)N_TOK * INNER];

// ---------------- helpers ----------------
__device__ __forceinline__ uint32_t s2u(const void* p) {
    return (uint32_t)__cvta_generic_to_shared(p);
}
__device__ __forceinline__ void cp16(uint32_t d, const void* g) {
    asm volatile("cp.async.cg.shared.global [%0],[%1],16;" :: "r"(d), "l"(g));
}
__device__ __forceinline__ void cpcommit() { asm volatile("cp.async.commit_group;"); }
template<int Nw> __device__ __forceinline__ void cpwait() {
    asm volatile("cp.async.wait_group %0;" :: "n"(Nw));
}
__device__ __forceinline__ void ldsm4(uint32_t* r, uint32_t addr) {
    asm volatile("ldmatrix.sync.aligned.m8n8.x4.shared.b16 {%0,%1,%2,%3},[%4];"
                 : "=r"(r[0]), "=r"(r[1]), "=r"(r[2]), "=r"(r[3]) : "r"(addr));
}
__device__ __forceinline__ void mma_f16(float* d, const uint32_t* a, uint32_t b0, uint32_t b1) {
    asm volatile(
        "mma.sync.aligned.m16n8k16.row.col.f32.f16.f16.f32 "
        "{%0,%1,%2,%3},{%4,%5,%6,%7},{%8,%9},{%0,%1,%2,%3};"
        : "+f"(d[0]), "+f"(d[1]), "+f"(d[2]), "+f"(d[3])
        : "r"(a[0]), "r"(a[1]), "r"(a[2]), "r"(a[3]), "r"(b0), "r"(b1));
}
__device__ __forceinline__ void split2h(float v, fp16& h, fp16& l) {
    h = __float2half_rn(v);
    l = __float2half_rn(v - __half2float(h));
}

// ---------------- layernorm + fp16 hi/lo split ----------------
__global__ void ln_split_kernel(const float* __restrict__ x,
                                const float* __restrict__ gam,
                                const float* __restrict__ bet,
                                fp16* __restrict__ oh, fp16* __restrict__ ol)
{
    int row = blockIdx.x;
    const float* xr = x + (size_t)row * DIMX;
    float s = 0.f, s2 = 0.f;
    for (int c = threadIdx.x; c < DIMX; c += blockDim.x) {
        float v = xr[c];
        s += v; s2 += v * v;
    }
    __shared__ float red[64];
    for (int o = 16; o > 0; o >>= 1) {
        s  += __shfl_xor_sync(0xffffffffu, s,  o);
        s2 += __shfl_xor_sync(0xffffffffu, s2, o);
    }
    int warp = threadIdx.x >> 5, lane = threadIdx.x & 31;
    int nwarp = blockDim.x >> 5;
    if (lane == 0) { red[warp] = s; red[warp + 32] = s2; }
    __syncthreads();
    if (warp == 0) {
        s  = (lane < nwarp) ? red[lane] : 0.f;
        s2 = (lane < nwarp) ? red[lane + 32] : 0.f;
        for (int o = 16; o > 0; o >>= 1) {
            s  += __shfl_xor_sync(0xffffffffu, s,  o);
            s2 += __shfl_xor_sync(0xffffffffu, s2, o);
        }
        if (lane == 0) { red[0] = s; red[1] = s2; }
    }
    __syncthreads();
    float mean = red[0] * (1.f / DIMX);
    float var  = red[1] * (1.f / DIMX) - mean * mean;
    float inv  = rsqrtf(var + 1e-5f);
    for (int c = threadIdx.x; c < DIMX; c += blockDim.x) {
        float y = (xr[c] - mean) * inv * gam[c] + bet[c];
        fp16 h, l; split2h(y, h, l);
        oh[(size_t)row * DIMX + c] = h;
        ol[(size_t)row * DIMX + c] = l;
    }
}

// ---------------- transpose to single fp16 ----------------
__global__ void tsingle_kernel(const float* __restrict__ in, int ldin, long long sIn,
                               fp16* __restrict__ o, int ldout, long long sOut,
                               int R, int C)
{
    __shared__ float t[32][33];
    in += (size_t)blockIdx.z * sIn;
    o  += (size_t)blockIdx.z * sOut;
    int r0 = blockIdx.y * 32, c0 = blockIdx.x * 32;
    int tx = threadIdx.x & 31, ty = threadIdx.x >> 5;
#pragma unroll
    for (int i = 0; i < 32; i += 8) {
        int r = r0 + ty + i;
        if (r < R && c0 + tx < C) t[ty + i][tx] = in[(size_t)r * ldin + c0 + tx];
    }
    __syncthreads();
#pragma unroll
    for (int i = 0; i < 32; i += 8) {
        int c = c0 + ty + i, r = r0 + tx;
        if (c < C && r < R)
            o[(size_t)c * ldout + r] = __float2half_rn(t[tx][ty + i]);
    }
}

// ---------------- remap: q -> hi/lo split, k -> single ----------------
__global__ void remap_split(const float* __restrict__ c12,
                            fp16* __restrict__ qh, fp16* __restrict__ ql,
                            fp16* __restrict__ k)
{
    int idx = blockIdx.x * blockDim.x + threadIdx.x;
    if (idx >= N_TOK * INNER) return;
    int i = idx >> 10, col = idx & 1023;
    int h = col >> 6, d = col & 63;
    float qv = c12[(size_t)i * NQKV + col];
    float kv = c12[(size_t)i * NQKV + INNER + col];
    size_t dst = ((size_t)h * N_TOK + i) * DHEAD + d;
    fp16 a, b;
    split2h(qv, a, b); qh[dst] = a; ql[dst] = b;
    k[dst] = __float2half_rn(kv);
}

// ---------------- fp16 tensor-core GEMM ----------------
// C = alpha * A @ B^T.  128 threads, warp grid (BM/WM) x (BN/WN) = 4 warps.
// ASPLIT: A hi/lo (adds al*b MMA).
// MODE 0: C fp32 (+bias). MODE 1: C single fp16. MODE 2: blend with Hm -> fp32.
template<int BM, int BN, int WM, int WN, int ASPLIT, int MODE>
__global__ void __launch_bounds__(128, 2)
gemm_f16(const fp16* __restrict__ Ahi, const fp16* __restrict__ Alo,
         const fp16* __restrict__ Bhi,
         float* __restrict__ C, fp16* __restrict__ Ch,
         const float* __restrict__ Hm,
         int K, int lda, int ldb, int ldc,
         long long sA, long long sB, long long sC,
         float alpha, const float* __restrict__ bias)
{
    constexpr int MI  = WM / 16;
    constexpr int NJ  = WN / 16;
    constexpr int NJ2 = WN / 8;
    constexpr int NAI = BM / 16;
    constexpr int NBI = BN / 16;
    constexpr int ABUF = (ASPLIT ? 2 : 1) * BM * 64;  // halves
    constexpr int BBUF = BN * 64;
    constexpr int SS   = ABUF + BBUF;
    constexpr int WNN = BN / WN;

    extern __shared__ fp16 sm[];

    Ahi += (size_t)blockIdx.z * sA;
    if (ASPLIT) Alo += (size_t)blockIdx.z * sA;
    Bhi += (size_t)blockIdx.z * sB;
    if (MODE == 1) Ch += (size_t)blockIdx.z * sC;
    else           C  += (size_t)blockIdx.z * sC;
    if (MODE == 2) Hm += (size_t)blockIdx.z * sC;

    const int bm = blockIdx.y * BM, bn = blockIdx.x * BN;
    const int tid = threadIdx.x, lane = tid & 31, wid = tid >> 5;
    const int wm0 = (wid / WNN) * WM, wn0 = (wid % WNN) * WN;

    float acc[MI][NJ2][4];
#pragma unroll
    for (int i = 0; i < MI; i++)
#pragma unroll
        for (int j = 0; j < NJ2; j++) {
            acc[i][j][0] = 0.f; acc[i][j][1] = 0.f;
            acc[i][j][2] = 0.f; acc[i][j][3] = 0.f;
        }

    auto issue = [&](int kt, int stg) {
        fp16* sA_hi = sm + stg * SS;
        fp16* sA_lo = sA_hi + BM * 64;
        fp16* sB_hi = sA_hi + ABUF;
#pragma unroll
        for (int i = 0; i < NAI; i++) {
            int id = tid + i * 128, r = id >> 3, c = id & 7;
            size_t go = (size_t)(bm + r) * lda + kt * 64 + c * 8;
            int so = r * 64 + ((c ^ (r & 7)) << 3);
            cp16(s2u(sA_hi + so), Ahi + go);
            if (ASPLIT) cp16(s2u(sA_lo + so), Alo + go);
        }
#pragma unroll
        for (int i = 0; i < NBI; i++) {
            int id = tid + i * 128, r = id >> 3, c = id & 7;
            size_t go = (size_t)(bn + r) * ldb + kt * 64 + c * 8;
            int so = r * 64 + ((c ^ (r & 7)) << 3);
            cp16(s2u(sB_hi + so), Bhi + go);
        }
    };

    const int KT = K >> 6;
    issue(0, 0); cpcommit();

    for (int kt = 0; kt < KT; kt++) {
        int cur = kt & 1;
        if (kt + 1 < KT) { issue(kt + 1, cur ^ 1); cpcommit(); cpwait<1>(); }
        else             { cpwait<0>(); }
        __syncthreads();

        const fp16* sA_hi = sm + cur * SS;
        const fp16* sA_lo = sA_hi + BM * 64;
        const fp16* sB_hi = sA_hi + ABUF;

#pragma unroll
        for (int s = 0; s < 4; s++) {
            const int c0 = 2 * s;
            uint32_t ah[MI][4], al[MI][4];
#pragma unroll
            for (int mi = 0; mi < MI; mi++) {
                int row = wm0 + mi * 16 + (lane & 15);
                int ch  = c0 + (lane >> 4);
                int off = row * 64 + ((ch ^ (row & 7)) << 3);
                ldsm4(ah[mi], s2u(sA_hi + off));
                if (ASPLIT) ldsm4(al[mi], s2u(sA_lo + off));
            }
#pragma unroll
            for (int nj = 0; nj < NJ; nj++) {
                int rowb = wn0 + nj * 16 + (lane & 15);
                int ch   = c0 + (lane >> 4);
                int off  = rowb * 64 + ((ch ^ (rowb & 7)) << 3);
                uint32_t bb[4];
                ldsm4(bb, s2u(sB_hi + off));
#pragma unroll
                for (int mi = 0; mi < MI; mi++) {
                    mma_f16(acc[mi][2 * nj],     ah[mi], bb[0], bb[2]);
                    mma_f16(acc[mi][2 * nj + 1], ah[mi], bb[1], bb[3]);
                    if (ASPLIT) {
                        mma_f16(acc[mi][2 * nj],     al[mi], bb[0], bb[2]);
                        mma_f16(acc[mi][2 * nj + 1], al[mi], bb[1], bb[3]);
                    }
                }
            }
        }
        __syncthreads();
    }

    // ---- epilogue ----
#pragma unroll
    for (int mi = 0; mi < MI; mi++) {
#pragma unroll
        for (int nj2 = 0; nj2 < NJ2; nj2++) {
            int r0  = bm + wm0 + mi * 16 + (lane >> 2);
            int col = bn + wn0 + nj2 * 8 + (lane & 3) * 2;
            float v0 = acc[mi][nj2][0] * alpha, v1 = acc[mi][nj2][1] * alpha;
            float v2 = acc[mi][nj2][2] * alpha, v3 = acc[mi][nj2][3] * alpha;
            size_t o0 = (size_t)r0 * ldc + col;
            size_t o1 = o0 + (size_t)8 * ldc;
            if (MODE == 1) {
                *(__half2*)&Ch[o0] = __halves2half2(__float2half_rn(v0), __float2half_rn(v1));
                *(__half2*)&Ch[o1] = __halves2half2(__float2half_rn(v2), __float2half_rn(v3));
            } else if (MODE == 2) {
                float2 ha = *(const float2*)&Hm[o0];
                float2 hb = *(const float2*)&Hm[o1];
                *(float2*)&C[o0] = make_float2(ALPHA_C * v0 + (1.f - ALPHA_C) * ha.x,
                                               ALPHA_C * v1 + (1.f - ALPHA_C) * ha.y);
                *(float2*)&C[o1] = make_float2(ALPHA_C * v2 + (1.f - ALPHA_C) * hb.x,
                                               ALPHA_C * v3 + (1.f - ALPHA_C) * hb.y);
            } else {
                if (bias) {
                    float b0 = bias[col], b1 = bias[col + 1];
                    v0 += b0; v1 += b1; v2 += b0; v3 += b1;
                }
                *(float2*)&C[o0] = make_float2(v0, v1);
                *(float2*)&C[o1] = make_float2(v2, v3);
            }
        }
    }
}

// ---------------- fused mix_pre + softmax + mix_post ----------------
// Pass A: fp32 float4 mix_pre (round-9 form). Pass B: probabilities in half2,
// mix_post via HFMA2 (attn feeds only the fp16 AV path).
__global__ void __launch_bounds__(512)
fused_softmax(const float* __restrict__ blended,
              const float* __restrict__ mpre, const float* __restrict__ mpost,
              fp16* __restrict__ at)
{
    extern __shared__ float sd[];
    __shared__ float smixA[HEADS * HEADS];
    __shared__ __half2 smixB2[HEADS * HEADS];
    __shared__ float redm[16][HEADS], redl[16][HEADS];
    __shared__ float fm[HEADS], fl[HEADS];

    const int i = blockIdx.x, tid = threadIdx.x;
    if (tid < 256) {
        smixA[tid] = mpre[tid];
        smixB2[tid] = __half2half2(__float2half_rn(mpost[tid]));
    }
    __syncthreads();

    const size_t sH = (size_t)N_TOK * N_TOK;
    const size_t hbase = (size_t)i * N_TOK;
    const int j = tid * 4;

    float4 bl4[HEADS];
#pragma unroll
    for (int h = 0; h < HEADS; h++)
        bl4[h] = *(const float4*)&blended[(size_t)h * sH + hbase + j];

    float m[HEADS], l[HEADS];
#pragma unroll
    for (int g = 0; g < HEADS; g++) {
        float4 d = make_float4(0.f, 0.f, 0.f, 0.f);
#pragma unroll
        for (int h = 0; h < HEADS; h++) {
            float w = smixA[h * HEADS + g];
            d.x += bl4[h].x * w; d.y += bl4[h].y * w;
            d.z += bl4[h].z * w; d.w += bl4[h].w * w;
        }
        *(float4*)&sd[g * N_TOK + j] = d;
        float mx = fmaxf(fmaxf(d.x, d.y), fmaxf(d.z, d.w));
        m[g] = mx;
        l[g] = __expf(d.x - mx) + __expf(d.y - mx)
             + __expf(d.z - mx) + __expf(d.w - mx);
    }

#pragma unroll
    for (int g = 0; g < HEADS; g++) {
        for (int o = 16; o > 0; o >>= 1) {
            float m2 = __shfl_xor_sync(0xffffffffu, m[g], o);
            float l2 = __shfl_xor_sync(0xffffffffu, l[g], o);
            float nm = fmaxf(m[g], m2);
            l[g] = l[g] * __expf(m[g] - nm) + l2 * __expf(m2 - nm);
            m[g] = nm;
        }
    }
    int warp = tid >> 5, lane = tid & 31;
    if (lane == 0) {
#pragma unroll
        for (int g = 0; g < HEADS; g++) { redm[warp][g] = m[g]; redl[warp][g] = l[g]; }
    }
    __syncthreads();
    if (tid < HEADS) {
        int g = tid;
        float M = redm[0][g], L = redl[0][g];
#pragma unroll
        for (int w = 1; w < 16; w++) {
            float m2 = redm[w][g], l2 = redl[w][g];
            float nm = fmaxf(M, m2);
            L = L * __expf(M - nm) + l2 * __expf(m2 - nm);
            M = nm;
        }
        fm[g] = M; fl[g] = 1.0f / L;
    }
    __syncthreads();

    // pass B: p -> half2, mix_post via HFMA2
    __half2 p01[HEADS], p23[HEADS];
#pragma unroll
    for (int h = 0; h < HEADS; h++) {
        float mh = fm[h], li = fl[h];
        float4 d = *(const float4*)&sd[h * N_TOK + j];
        p01[h] = __floats2half2_rn(__expf(d.x - mh) * li, __expf(d.y - mh) * li);
        p23[h] = __floats2half2_rn(__expf(d.z - mh) * li, __expf(d.w - mh) * li);
    }
    const size_t rbase = (size_t)i * (HEADS * N_TOK);
#pragma unroll
    for (int g = 0; g < HEADS; g++) {
        __half2 a01 = __float2half2_rn(0.f), a23 = __float2half2_rn(0.f);
#pragma unroll
        for (int h = 0; h < HEADS; h++) {
            __half2 w2 = smixB2[h * HEADS + g];
            a01 = __hfma2(p01[h], w2, a01);
            a23 = __hfma2(p23[h], w2, a23);
        }
        size_t o = rbase + g * N_TOK + j;
        ((__half2*)&at[o])[0] = a01;
        ((__half2*)&at[o])[1] = a23;
    }
}

// ---------------- launch ----------------
extern "C" void kernel_launch(void* const* d_in, const int* in_sizes, int n_in,
                              void* d_out, int out_size)
{
    const float* x        = (const float*)d_in[0];
    const float* h_in     = (const float*)d_in[1];
    const float* ln_g     = (const float*)d_in[2];
    const float* ln_b     = (const float*)d_in[3];
    const float* Wq       = (const float*)d_in[4];
    const float* Wkv      = (const float*)d_in[5];
    const float* mix_pre  = (const float*)d_in[6];
    const float* mix_post = (const float*)d_in[7];
    const float* Wout     = (const float*)d_in[8];
    const float* bout     = (const float*)d_in[9];

    float* out = (float*)d_out;
    float* blended_out = out + (size_t)N_TOK * DIMX;

    float* c12;
    fp16 *xnh, *xnl, *wqkv, *wo, *qh, *ql, *k, *vt, *at, *ao;
    cudaGetSymbolAddress((void**)&c12,  g_c12);
    cudaGetSymbolAddress((void**)&xnh,  g_xnh);
    cudaGetSymbolAddress((void**)&xnl,  g_xnl);
    cudaGetSymbolAddress((void**)&wqkv, g_wqkv);
    cudaGetSymbolAddress((void**)&wo,   g_wo);
    cudaGetSymbolAddress((void**)&qh,   g_qh);
    cudaGetSymbolAddress((void**)&ql,   g_ql);
    cudaGetSymbolAddress((void**)&k,    g_k);
    cudaGetSymbolAddress((void**)&vt,   g_vt);
    cudaGetSymbolAddress((void**)&at,   g_at);
    cudaGetSymbolAddress((void**)&ao,   g_ao);

    // smem sizes (bytes)
    const int SM_QKV = 2 * (2 * 128 + 128) * 128;   // 98304 (A split, 2 stg)
    const int SM_QK  = (2 * 128 + 128) * 128;       // 49152 (A split, KT=1, 1 stg)
    const int SM_AV  = 2 * (128 + 64) * 128;        // 49152 (no split, 2 stg)
    const int SM_SOFT = HEADS * N_TOK * 4;          // 131072
    cudaFuncSetAttribute(gemm_f16<128, 128, 64, 64, 1, 0>,
                         cudaFuncAttributeMaxDynamicSharedMemorySize, SM_QKV);
    cudaFuncSetAttribute(gemm_f16<128, 128, 64, 64, 1, 2>,
                         cudaFuncAttributeMaxDynamicSharedMemorySize, SM_QK);
    cudaFuncSetAttribute(gemm_f16<128, 64, 64, 32, 0, 1>,
                         cudaFuncAttributeMaxDynamicSharedMemorySize, SM_AV);
    cudaFuncSetAttribute(gemm_f16<128, 64, 64, 32, 0, 0>,
                         cudaFuncAttributeMaxDynamicSharedMemorySize, SM_AV);
    cudaFuncSetAttribute(fused_softmax,
                         cudaFuncAttributeMaxDynamicSharedMemorySize, SM_SOFT);

    // 1. layernorm + fp16 split
    ln_split_kernel<<<N_TOK, 256>>>(x, ln_g, ln_b, xnh, xnl);

    // 2. weight transposes -> single fp16 K-major
    tsingle_kernel<<<dim3(32, 32, 1), 256>>>(Wq, INNER, 0, wqkv, DIMX, 0, DIMX, INNER);
    tsingle_kernel<<<dim3(64, 32, 1), 256>>>(Wkv, 2 * INNER, 0,
                                             wqkv + (size_t)INNER * DIMX, DIMX, 0,
                                             DIMX, 2 * INNER);
    tsingle_kernel<<<dim3(32, 32, 1), 256>>>(Wout, DIMX, 0, wo, INNER, 0, INNER, DIMX);

    // 3. c12 = xn @ [Wq|Wkv]  (M=2048, N=3072, K=1024)  A-split 2-MMA
    gemm_f16<128, 128, 64, 64, 1, 0><<<dim3(NQKV / 128, N_TOK / 128, 1), 128, SM_QKV>>>(
        xnh, xnl, wqkv, c12, nullptr, nullptr,
        DIMX, DIMX, DIMX, NQKV, 0, 0, 0, 1.f, nullptr);

    // 4. remap q hi/lo, k single; 5. v^T single
    remap_split<<<(N_TOK * INNER + 255) / 256, 256>>>(c12, qh, ql, k);
    tsingle_kernel<<<dim3(2, 64, HEADS), 256>>>(c12 + 2 * INNER, NQKV, DHEAD,
                                                vt, N_TOK, (long long)DHEAD * N_TOK,
                                                N_TOK, DHEAD);

    // 6. blended[h][i][j] = 0.45*SCALE*(q@k^T) + 0.55*h  (A-split 2-MMA)
    gemm_f16<128, 128, 64, 64, 1, 2><<<dim3(N_TOK / 128, N_TOK / 128, HEADS), 128, SM_QK>>>(
        qh, ql, k, blended_out, nullptr, h_in,
        DHEAD, DHEAD, DHEAD, N_TOK,
        (long long)N_TOK * DHEAD, (long long)N_TOK * DHEAD,
        (long long)N_TOK * N_TOK,
        SCALE_C, nullptr);

    // 7. fused mix_pre + softmax + mix_post -> attn single fp16 [i][g][j]
    fused_softmax<<<N_TOK, 512, SM_SOFT>>>(blended_out, mix_pre, mix_post, at);

    // 8. ao = attn @ v  (per head; M=2048, N=64, K=2048) 1-MMA -> single fp16
    gemm_f16<128, 64, 64, 32, 0, 1><<<dim3(1, N_TOK / 128, HEADS), 128, SM_AV>>>(
        at, nullptr, vt, nullptr, ao, nullptr,
        N_TOK, HEADS * N_TOK, N_TOK, INNER,
        (long long)N_TOK, (long long)DHEAD * N_TOK, (long long)DHEAD,
        1.f, nullptr);

    // 9. out = ao @ Wout + bout  (M=2048, N=1024, K=1024) 1-MMA, BN=64 (256 CTAs)
    gemm_f16<128, 64, 64, 32, 0, 0><<<dim3(DIMX / 64, N_TOK / 128, 1), 128, SM_AV>>>(
        ao, nullptr, wo, out, nullptr, nullptr,
        INNER, INNER, INNER, DIMX, 0, 0, 0, 1.f, bout);

    (void)in_sizes; (void)n_in; (void)out_size;
}

// round 14
// speedup vs baseline: 1.1370x; 1.0519x over previous
#include <cuda_runtime.h>
#include <cuda_fp16.h>
#include <math.h>
#include <stdint.h>

#define N_TOK 2048
#define DIMX  1024
#define HEADS 16
#define DHEAD 64
#define INNER 1024
#define NQKV  3072
#define ALPHA_C 0.45f
#define SCALE_C 0.125f

typedef __half fp16;

// ---------------- device buffers ----------------
__device__ __align__(256) float g_c12[(size_t)N_TOK * NQKV];
__device__ __align__(256) fp16  g_xnh[(size_t)N_TOK * DIMX];
__device__ __align__(256) fp16  g_xnl[(size_t)N_TOK * DIMX];
__device__ __align__(256) fp16  g_wqkv[(size_t)NQKV * DIMX];
__device__ __align__(256) fp16  g_wo[(size_t)DIMX * INNER];
__device__ __align__(256) fp16  g_qh[(size_t)HEADS * N_TOK * DHEAD];
__device__ __align__(256) fp16  g_ql[(size_t)HEADS * N_TOK * DHEAD];
__device__ __align__(256) fp16  g_k[(size_t)HEADS * N_TOK * DHEAD];
__device__ __align__(256) fp16  g_vt[(size_t)HEADS * DHEAD * N_TOK];
__device__ __align__(256) fp16  g_at[(size_t)HEADS * N_TOK * N_TOK];  // [i][g][j]
__device__ __align__(256) fp16  g_ao[(size_t)N_TOK * INNER];

// ---------------- helpers ----------------
__device__ __forceinline__ uint32_t s2u(const void* p) {
    return (uint32_t)__cvta_generic_to_shared(p);
}
__device__ __forceinline__ void cp16(uint32_t d, const void* g) {
    asm volatile("cp.async.cg.shared.global [%0],[%1],16;" :: "r"(d), "l"(g));
}
__device__ __forceinline__ void cpcommit() { asm volatile("cp.async.commit_group;"); }
template<int Nw> __device__ __forceinline__ void cpwait() {
    asm volatile("cp.async.wait_group %0;" :: "n"(Nw));
}
__device__ __forceinline__ void ldsm4(uint32_t* r, uint32_t addr) {
    asm volatile("ldmatrix.sync.aligned.m8n8.x4.shared.b16 {%0,%1,%2,%3},[%4];"
                 : "=r"(r[0]), "=r"(r[1]), "=r"(r[2]), "=r"(r[3]) : "r"(addr));
}
__device__ __forceinline__ void mma_f16(float* d, const uint32_t* a, uint32_t b0, uint32_t b1) {
    asm volatile(
        "mma.sync.aligned.m16n8k16.row.col.f32.f16.f16.f32 "
        "{%0,%1,%2,%3},{%4,%5,%6,%7},{%8,%9},{%0,%1,%2,%3};"
        : "+f"(d[0]), "+f"(d[1]), "+f"(d[2]), "+f"(d[3])
        : "r"(a[0]), "r"(a[1]), "r"(a[2]), "r"(a[3]), "r"(b0), "r"(b1));
}
__device__ __forceinline__ void split2h(float v, fp16& h, fp16& l) {
    h = __float2half_rn(v);
    l = __float2half_rn(v - __half2float(h));
}

// ---------------- layernorm + fp16 hi/lo split ----------------
__global__ void ln_split_kernel(const float* __restrict__ x,
                                const float* __restrict__ gam,
                                const float* __restrict__ bet,
                                fp16* __restrict__ oh, fp16* __restrict__ ol)
{
    int row = blockIdx.x;
    const float* xr = x + (size_t)row * DIMX;
    float s = 0.f, s2 = 0.f;
    for (int c = threadIdx.x; c < DIMX; c += blockDim.x) {
        float v = xr[c];
        s += v; s2 += v * v;
    }
    __shared__ float red[64];
    for (int o = 16; o > 0; o >>= 1) {
        s  += __shfl_xor_sync(0xffffffffu, s,  o);
        s2 += __shfl_xor_sync(0xffffffffu, s2, o);
    }
    int warp = threadIdx.x >> 5, lane = threadIdx.x & 31;
    int nwarp = blockDim.x >> 5;
    if (lane == 0) { red[warp] = s; red[warp + 32] = s2; }
    __syncthreads();
    if (warp == 0) {
        s  = (lane < nwarp) ? red[lane] : 0.f;
        s2 = (lane < nwarp) ? red[lane + 32] : 0.f;
        for (int o = 16; o > 0; o >>= 1) {
            s  += __shfl_xor_sync(0xffffffffu, s,  o);
            s2 += __shfl_xor_sync(0xffffffffu, s2, o);
        }
        if (lane == 0) { red[0] = s; red[1] = s2; }
    }
    __syncthreads();
    float mean = red[0] * (1.f / DIMX);
    float var  = red[1] * (1.f / DIMX) - mean * mean;
    float inv  = rsqrtf(var + 1e-5f);
    for (int c = threadIdx.x; c < DIMX; c += blockDim.x) {
        float y = (xr[c] - mean) * inv * gam[c] + bet[c];
        fp16 h, l; split2h(y, h, l);
        oh[(size_t)row * DIMX + c] = h;
        ol[(size_t)row * DIMX + c] = l;
    }
}

// ---------------- transpose to single fp16 ----------------
__global__ void tsingle_kernel(const float* __restrict__ in, int ldin, long long sIn,
                               fp16* __restrict__ o, int ldout, long long sOut,
                               int R, int C)
{
    __shared__ float t[32][33];
    in += (size_t)blockIdx.z * sIn;
    o  += (size_t)blockIdx.z * sOut;
    int r0 = blockIdx.y * 32, c0 = blockIdx.x * 32;
    int tx = threadIdx.x & 31, ty = threadIdx.x >> 5;
#pragma unroll
    for (int i = 0; i < 32; i += 8) {
        int r = r0 + ty + i;
        if (r < R && c0 + tx < C) t[ty + i][tx] = in[(size_t)r * ldin + c0 + tx];
    }
    __syncthreads();
#pragma unroll
    for (int i = 0; i < 32; i += 8) {
        int c = c0 + ty + i, r = r0 + tx;
        if (c < C && r < R)
            o[(size_t)c * ldout + r] = __float2half_rn(t[tx][ty + i]);
    }
}

// ---------------- remap: q -> hi/lo split, k -> single ----------------
__global__ void remap_split(const float* __restrict__ c12,
                            fp16* __restrict__ qh, fp16* __restrict__ ql,
                            fp16* __restrict__ k)
{
    int idx = blockIdx.x * blockDim.x + threadIdx.x;
    if (idx >= N_TOK * INNER) return;
    int i = idx >> 10, col = idx & 1023;
    int h = col >> 6, d = col & 63;
    float qv = c12[(size_t)i * NQKV + col];
    float kv = c12[(size_t)i * NQKV + INNER + col];
    size_t dst = ((size_t)h * N_TOK + i) * DHEAD + d;
    fp16 a, b;
    split2h(qv, a, b); qh[dst] = a; ql[dst] = b;
    k[dst] = __float2half_rn(kv);
}

// ---------------- fp16 tensor-core GEMM ----------------
// C = alpha * A @ B^T.  128 threads, warp grid (BM/WM) x (BN/WN) = 4 warps.
// ASPLIT: A hi/lo (adds al*b MMA).
// MODE 0: C fp32 (+bias). MODE 1: C single fp16. MODE 2: blend with Hm -> fp32.
template<int BM, int BN, int WM, int WN, int ASPLIT, int MODE>
__global__ void __launch_bounds__(128, 2)
gemm_f16(const fp16* __restrict__ Ahi, const fp16* __restrict__ Alo,
         const fp16* __restrict__ Bhi,
         float* __restrict__ C, fp16* __restrict__ Ch,
         const float* __restrict__ Hm,
         int K, int lda, int ldb, int ldc,
         long long sA, long long sB, long long sC,
         float alpha, const float* __restrict__ bias)
{
    constexpr int MI  = WM / 16;
    constexpr int NJ  = WN / 16;
    constexpr int NJ2 = WN / 8;
    constexpr int NAI = BM / 16;
    constexpr int NBI = BN / 16;
    constexpr int ABUF = (ASPLIT ? 2 : 1) * BM * 64;  // halves
    constexpr int BBUF = BN * 64;
    constexpr int SS   = ABUF + BBUF;
    constexpr int WNN = BN / WN;

    extern __shared__ fp16 sm[];

    Ahi += (size_t)blockIdx.z * sA;
    if (ASPLIT) Alo += (size_t)blockIdx.z * sA;
    Bhi += (size_t)blockIdx.z * sB;
    if (MODE == 1) Ch += (size_t)blockIdx.z * sC;
    else           C  += (size_t)blockIdx.z * sC;
    if (MODE == 2) Hm += (size_t)blockIdx.z * sC;

    const int bm = blockIdx.y * BM, bn = blockIdx.x * BN;
    const int tid = threadIdx.x, lane = tid & 31, wid = tid >> 5;
    const int wm0 = (wid / WNN) * WM, wn0 = (wid % WNN) * WN;

    float acc[MI][NJ2][4];
#pragma unroll
    for (int i = 0; i < MI; i++)
#pragma unroll
        for (int j = 0; j < NJ2; j++) {
            acc[i][j][0] = 0.f; acc[i][j][1] = 0.f;
            acc[i][j][2] = 0.f; acc[i][j][3] = 0.f;
        }

    auto issue = [&](int kt, int stg) {
        fp16* sA_hi = sm + stg * SS;
        fp16* sA_lo = sA_hi + BM * 64;
        fp16* sB_hi = sA_hi + ABUF;
#pragma unroll
        for (int i = 0; i < NAI; i++) {
            int id = tid + i * 128, r = id >> 3, c = id & 7;
            size_t go = (size_t)(bm + r) * lda + kt * 64 + c * 8;
            int so = r * 64 + ((c ^ (r & 7)) << 3);
            cp16(s2u(sA_hi + so), Ahi + go);
            if (ASPLIT) cp16(s2u(sA_lo + so), Alo + go);
        }
#pragma unroll
        for (int i = 0; i < NBI; i++) {
            int id = tid + i * 128, r = id >> 3, c = id & 7;
            size_t go = (size_t)(bn + r) * ldb + kt * 64 + c * 8;
            int so = r * 64 + ((c ^ (r & 7)) << 3);
            cp16(s2u(sB_hi + so), Bhi + go);
        }
    };

    const int KT = K >> 6;
    issue(0, 0); cpcommit();

    for (int kt = 0; kt < KT; kt++) {
        int cur = kt & 1;
        if (kt + 1 < KT) { issue(kt + 1, cur ^ 1); cpcommit(); cpwait<1>(); }
        else             { cpwait<0>(); }
        __syncthreads();

        const fp16* sA_hi = sm + cur * SS;
        const fp16* sA_lo = sA_hi + BM * 64;
        const fp16* sB_hi = sA_hi + ABUF;

#pragma unroll
        for (int s = 0; s < 4; s++) {
            const int c0 = 2 * s;
            uint32_t ah[MI][4], al[MI][4];
#pragma unroll
            for (int mi = 0; mi < MI; mi++) {
                int row = wm0 + mi * 16 + (lane & 15);
                int ch  = c0 + (lane >> 4);
                int off = row * 64 + ((ch ^ (row & 7)) << 3);
                ldsm4(ah[mi], s2u(sA_hi + off));
                if (ASPLIT) ldsm4(al[mi], s2u(sA_lo + off));
            }
#pragma unroll
            for (int nj = 0; nj < NJ; nj++) {
                int rowb = wn0 + nj * 16 + (lane & 15);
                int ch   = c0 + (lane >> 4);
                int off  = rowb * 64 + ((ch ^ (rowb & 7)) << 3);
                uint32_t bb[4];
                ldsm4(bb, s2u(sB_hi + off));
#pragma unroll
                for (int mi = 0; mi < MI; mi++) {
                    mma_f16(acc[mi][2 * nj],     ah[mi], bb[0], bb[2]);
                    mma_f16(acc[mi][2 * nj + 1], ah[mi], bb[1], bb[3]);
                    if (ASPLIT) {
                        mma_f16(acc[mi][2 * nj],     al[mi], bb[0], bb[2]);
                        mma_f16(acc[mi][2 * nj + 1], al[mi], bb[1], bb[3]);
                    }
                }
            }
        }
        __syncthreads();
    }

    // ---- epilogue ----
#pragma unroll
    for (int mi = 0; mi < MI; mi++) {
#pragma unroll
        for (int nj2 = 0; nj2 < NJ2; nj2++) {
            int r0  = bm + wm0 + mi * 16 + (lane >> 2);
            int col = bn + wn0 + nj2 * 8 + (lane & 3) * 2;
            float v0 = acc[mi][nj2][0] * alpha, v1 = acc[mi][nj2][1] * alpha;
            float v2 = acc[mi][nj2][2] * alpha, v3 = acc[mi][nj2][3] * alpha;
            size_t o0 = (size_t)r0 * ldc + col;
            size_t o1 = o0 + (size_t)8 * ldc;
            if (MODE == 1) {
                *(__half2*)&Ch[o0] = __halves2half2(__float2half_rn(v0), __float2half_rn(v1));
                *(__half2*)&Ch[o1] = __halves2half2(__float2half_rn(v2), __float2half_rn(v3));
            } else if (MODE == 2) {
                float2 ha = *(const float2*)&Hm[o0];
                float2 hb = *(const float2*)&Hm[o1];
                *(float2*)&C[o0] = make_float2(ALPHA_C * v0 + (1.f - ALPHA_C) * ha.x,
                                               ALPHA_C * v1 + (1.f - ALPHA_C) * ha.y);
                *(float2*)&C[o1] = make_float2(ALPHA_C * v2 + (1.f - ALPHA_C) * hb.x,
                                               ALPHA_C * v3 + (1.f - ALPHA_C) * hb.y);
            } else {
                if (bias) {
                    float b0 = bias[col], b1 = bias[col + 1];
                    v0 += b0; v1 += b1; v2 += b0; v3 += b1;
                }
                *(float2*)&C[o0] = make_float2(v0, v1);
                *(float2*)&C[o1] = make_float2(v2, v3);
            }
        }
    }
}

// ---------------- fused mix_pre + softmax + mix_post ----------------
// Pass A: fp32 float4 mix_pre. Stats: smem-transposed reduction — warp w
// reduces head w (replaces the 16x5 per-thread shuffle chain).
// Pass B: probabilities in half2, mix_post via HFMA2.
__global__ void __launch_bounds__(512)
fused_softmax(const float* __restrict__ blended,
              const float* __restrict__ mpre, const float* __restrict__ mpost,
              fp16* __restrict__ at)
{
    extern __shared__ float sd[];                        // [16][2048] mixed dots
    float* redM = sd + HEADS * N_TOK;                    // [16][512]
    float* redL = redM + HEADS * 512;                    // [16][512]
    __shared__ float smixA[HEADS * HEADS];
    __shared__ __half2 smixB2[HEADS * HEADS];
    __shared__ float fm[HEADS], fl[HEADS];

    const int i = blockIdx.x, tid = threadIdx.x;
    const int warp = tid >> 5, lane = tid & 31;
    if (tid < 256) {
        smixA[tid] = mpre[tid];
        smixB2[tid] = __half2half2(__float2half_rn(mpost[tid]));
    }
    __syncthreads();

    const size_t sH = (size_t)N_TOK * N_TOK;
    const size_t hbase = (size_t)i * N_TOK;
    const int j = tid * 4;

    float4 bl4[HEADS];
#pragma unroll
    for (int h = 0; h < HEADS; h++)
        bl4[h] = *(const float4*)&blended[(size_t)h * sH + hbase + j];

    float m[HEADS], l[HEADS];
#pragma unroll
    for (int g = 0; g < HEADS; g++) {
        float4 d = make_float4(0.f, 0.f, 0.f, 0.f);
#pragma unroll
        for (int h = 0; h < HEADS; h++) {
            float w = smixA[h * HEADS + g];
            d.x += bl4[h].x * w; d.y += bl4[h].y * w;
            d.z += bl4[h].z * w; d.w += bl4[h].w * w;
        }
        *(float4*)&sd[g * N_TOK + j] = d;
        float mx = fmaxf(fmaxf(d.x, d.y), fmaxf(d.z, d.w));
        m[g] = mx;
        l[g] = __expf(d.x - mx) + __expf(d.y - mx)
             + __expf(d.z - mx) + __expf(d.w - mx);
    }

    // ---- smem-transposed stats reduction: warp w reduces head w ----
#pragma unroll
    for (int g = 0; g < HEADS; g++) { redM[g * 512 + tid] = m[g]; redL[g * 512 + tid] = l[g]; }
    __syncthreads();
    {
        int g = warp;                         // 16 warps == 16 heads
        float M = redM[g * 512 + lane], L = redL[g * 512 + lane];
#pragma unroll
        for (int r = 1; r < 16; r++) {
            float m2 = redM[g * 512 + lane + r * 32];
            float l2 = redL[g * 512 + lane + r * 32];
            float nm = fmaxf(M, m2);
            L = L * __expf(M - nm) + l2 * __expf(m2 - nm);
            M = nm;
        }
        for (int o = 16; o > 0; o >>= 1) {
            float m2 = __shfl_xor_sync(0xffffffffu, M, o);
            float l2 = __shfl_xor_sync(0xffffffffu, L, o);
            float nm = fmaxf(M, m2);
            L = L * __expf(M - nm) + l2 * __expf(m2 - nm);
            M = nm;
        }
        if (lane == 0) { fm[g] = M; fl[g] = 1.0f / L; }
    }
    __syncthreads();

    // ---- pass B: p -> half2, mix_post via HFMA2 ----
    __half2 p01[HEADS], p23[HEADS];
#pragma unroll
    for (int h = 0; h < HEADS; h++) {
        float mh = fm[h], li = fl[h];
        float4 d = *(const float4*)&sd[h * N_TOK + j];
        p01[h] = __floats2half2_rn(__expf(d.x - mh) * li, __expf(d.y - mh) * li);
        p23[h] = __floats2half2_rn(__expf(d.z - mh) * li, __expf(d.w - mh) * li);
    }
    const size_t rbase = (size_t)i * (HEADS * N_TOK);
#pragma unroll
    for (int g = 0; g < HEADS; g++) {
        __half2 a01 = __float2half2_rn(0.f), a23 = __float2half2_rn(0.f);
#pragma unroll
        for (int h = 0; h < HEADS; h++) {
            __half2 w2 = smixB2[h * HEADS + g];
            a01 = __hfma2(p01[h], w2, a01);
            a23 = __hfma2(p23[h], w2, a23);
        }
        size_t o = rbase + g * N_TOK + j;
        ((__half2*)&at[o])[0] = a01;
        ((__half2*)&at[o])[1] = a23;
    }
}

// ---------------- launch ----------------
extern "C" void kernel_launch(void* const* d_in, const int* in_sizes, int n_in,
                              void* d_out, int out_size)
{
    const float* x        = (const float*)d_in[0];
    const float* h_in     = (const float*)d_in[1];
    const float* ln_g     = (const float*)d_in[2];
    const float* ln_b     = (const float*)d_in[3];
    const float* Wq       = (const float*)d_in[4];
    const float* Wkv      = (const float*)d_in[5];
    const float* mix_pre  = (const float*)d_in[6];
    const float* mix_post = (const float*)d_in[7];
    const float* Wout     = (const float*)d_in[8];
    const float* bout     = (const float*)d_in[9];

    float* out = (float*)d_out;
    float* blended_out = out + (size_t)N_TOK * DIMX;

    float* c12;
    fp16 *xnh, *xnl, *wqkv, *wo, *qh, *ql, *k, *vt, *at, *ao;
    cudaGetSymbolAddress((void**)&c12,  g_c12);
    cudaGetSymbolAddress((void**)&xnh,  g_xnh);
    cudaGetSymbolAddress((void**)&xnl,  g_xnl);
    cudaGetSymbolAddress((void**)&wqkv, g_wqkv);
    cudaGetSymbolAddress((void**)&wo,   g_wo);
    cudaGetSymbolAddress((void**)&qh,   g_qh);
    cudaGetSymbolAddress((void**)&ql,   g_ql);
    cudaGetSymbolAddress((void**)&k,    g_k);
    cudaGetSymbolAddress((void**)&vt,   g_vt);
    cudaGetSymbolAddress((void**)&at,   g_at);
    cudaGetSymbolAddress((void**)&ao,   g_ao);

    // smem sizes (bytes)
    const int SM_QKV = 2 * (2 * 128 + 128) * 128;   // 98304 (A split, 2 stg)
    const int SM_QK  = (2 * 128 + 128) * 128;       // 49152 (A split, KT=1, 1 stg)
    const int SM_AV  = 2 * (128 + 64) * 128;        // 49152 (no split, 2 stg)
    const int SM_SOFT = HEADS * N_TOK * 4 + 2 * HEADS * 512 * 4;  // 196608
    cudaFuncSetAttribute(gemm_f16<128, 128, 64, 64, 1, 0>,
                         cudaFuncAttributeMaxDynamicSharedMemorySize, SM_QKV);
    cudaFuncSetAttribute(gemm_f16<128, 128, 64, 64, 1, 2>,
                         cudaFuncAttributeMaxDynamicSharedMemorySize, SM_QK);
    cudaFuncSetAttribute(gemm_f16<128, 64, 64, 32, 0, 1>,
                         cudaFuncAttributeMaxDynamicSharedMemorySize, SM_AV);
    cudaFuncSetAttribute(gemm_f16<128, 64, 64, 32, 0, 0>,
                         cudaFuncAttributeMaxDynamicSharedMemorySize, SM_AV);
    cudaFuncSetAttribute(fused_softmax,
                         cudaFuncAttributeMaxDynamicSharedMemorySize, SM_SOFT);

    // 1. layernorm + fp16 split
    ln_split_kernel<<<N_TOK, 256>>>(x, ln_g, ln_b, xnh, xnl);

    // 2. weight transposes -> single fp16 K-major
    tsingle_kernel<<<dim3(32, 32, 1), 256>>>(Wq, INNER, 0, wqkv, DIMX, 0, DIMX, INNER);
    tsingle_kernel<<<dim3(64, 32, 1), 256>>>(Wkv, 2 * INNER, 0,
                                             wqkv + (size_t)INNER * DIMX, DIMX, 0,
                                             DIMX, 2 * INNER);
    tsingle_kernel<<<dim3(32, 32, 1), 256>>>(Wout, DIMX, 0, wo, INNER, 0, INNER, DIMX);

    // 3. c12 = xn @ [Wq|Wkv]  (M=2048, N=3072, K=1024)  A-split 2-MMA
    gemm_f16<128, 128, 64, 64, 1, 0><<<dim3(NQKV / 128, N_TOK / 128, 1), 128, SM_QKV>>>(
        xnh, xnl, wqkv, c12, nullptr, nullptr,
        DIMX, DIMX, DIMX, NQKV, 0, 0, 0, 1.f, nullptr);

    // 4. remap q hi/lo, k single; 5. v^T single
    remap_split<<<(N_TOK * INNER + 255) / 256, 256>>>(c12, qh, ql, k);
    tsingle_kernel<<<dim3(2, 64, HEADS), 256>>>(c12 + 2 * INNER, NQKV, DHEAD,
                                                vt, N_TOK, (long long)DHEAD * N_TOK,
                                                N_TOK, DHEAD);

    // 6. blended[h][i][j] = 0.45*SCALE*(q@k^T) + 0.55*h  (A-split 2-MMA)
    gemm_f16<128, 128, 64, 64, 1, 2><<<dim3(N_TOK / 128, N_TOK / 128, HEADS), 128, SM_QK>>>(
        qh, ql, k, blended_out, nullptr, h_in,
        DHEAD, DHEAD, DHEAD, N_TOK,
        (long long)N_TOK * DHEAD, (long long)N_TOK * DHEAD,
        (long long)N_TOK * N_TOK,
        SCALE_C, nullptr);

    // 7. fused mix_pre + softmax + mix_post -> attn single fp16 [i][g][j]
    fused_softmax<<<N_TOK, 512, SM_SOFT>>>(blended_out, mix_pre, mix_post, at);

    // 8. ao = attn @ v  (per head; M=2048, N=64, K=2048) 1-MMA -> single fp16
    gemm_f16<128, 64, 64, 32, 0, 1><<<dim3(1, N_TOK / 128, HEADS), 128, SM_AV>>>(
        at, nullptr, vt, nullptr, ao, nullptr,
        N_TOK, HEADS * N_TOK, N_TOK, INNER,
        (long long)N_TOK, (long long)DHEAD * N_TOK, (long long)DHEAD,
        1.f, nullptr);

    // 9. out = ao @ Wout + bout  (M=2048, N=1024, K=1024) 1-MMA, BN=64 (256 CTAs)
    gemm_f16<128, 64, 64, 32, 0, 0><<<dim3(DIMX / 64, N_TOK / 128, 1), 128, SM_AV>>>(
        ao, nullptr, wo, out, nullptr, nullptr,
        INNER, INNER, INNER, DIMX, 0, 0, 0, 1.f, bout);

    (void)in_sizes; (void)n_in; (void)out_size;
}

// round 15
// speedup vs baseline: 1.1424x; 1.0047x over previous
#include <cuda_runtime.h>
#include <cuda_fp16.h>
#include <math.h>
#include <stdint.h>

#define N_TOK 2048
#define DIMX  1024
#define HEADS 16
#define DHEAD 64
#define INNER 1024
#define NQKV  3072
#define ALPHA_C 0.45f
#define SCALE_C 0.125f

typedef __half fp16;

// ---------------- device buffers ----------------
__device__ __align__(256) float g_c12[(size_t)N_TOK * NQKV];
__device__ __align__(256) fp16  g_xnh[(size_t)N_TOK * DIMX];
__device__ __align__(256) fp16  g_xnl[(size_t)N_TOK * DIMX];
__device__ __align__(256) fp16  g_wqkv[(size_t)NQKV * DIMX];
__device__ __align__(256) fp16  g_wo[(size_t)DIMX * INNER];
__device__ __align__(256) fp16  g_qh[(size_t)HEADS * N_TOK * DHEAD];
__device__ __align__(256) fp16  g_ql[(size_t)HEADS * N_TOK * DHEAD];
__device__ __align__(256) fp16  g_k[(size_t)HEADS * N_TOK * DHEAD];
__device__ __align__(256) fp16  g_vt[(size_t)HEADS * DHEAD * N_TOK];
__device__ __align__(256) fp16  g_at[(size_t)HEADS * N_TOK * N_TOK];  // [i][g][j]
__device__ __align__(256) fp16  g_ao[(size_t)N_TOK * INNER];

// ---------------- helpers ----------------
__device__ __forceinline__ uint32_t s2u(const void* p) {
    return (uint32_t)__cvta_generic_to_shared(p);
}
__device__ __forceinline__ void cp16(uint32_t d, const void* g) {
    asm volatile("cp.async.cg.shared.global [%0],[%1],16;" :: "r"(d), "l"(g));
}
__device__ __forceinline__ void cpcommit() { asm volatile("cp.async.commit_group;"); }
template<int Nw> __device__ __forceinline__ void cpwait() {
    asm volatile("cp.async.wait_group %0;" :: "n"(Nw));
}
__device__ __forceinline__ void ldsm4(uint32_t* r, uint32_t addr) {
    asm volatile("ldmatrix.sync.aligned.m8n8.x4.shared.b16 {%0,%1,%2,%3},[%4];"
                 : "=r"(r[0]), "=r"(r[1]), "=r"(r[2]), "=r"(r[3]) : "r"(addr));
}
__device__ __forceinline__ void mma_f16(float* d, const uint32_t* a, uint32_t b0, uint32_t b1) {
    asm volatile(
        "mma.sync.aligned.m16n8k16.row.col.f32.f16.f16.f32 "
        "{%0,%1,%2,%3},{%4,%5,%6,%7},{%8,%9},{%0,%1,%2,%3};"
        : "+f"(d[0]), "+f"(d[1]), "+f"(d[2]), "+f"(d[3])
        : "r"(a[0]), "r"(a[1]), "r"(a[2]), "r"(a[3]), "r"(b0), "r"(b1));
}
__device__ __forceinline__ void split2h(float v, fp16& h, fp16& l) {
    h = __float2half_rn(v);
    l = __float2half_rn(v - __half2float(h));
}

// ---------------- layernorm + fp16 hi/lo split ----------------
__global__ void ln_split_kernel(const float* __restrict__ x,
                                const float* __restrict__ gam,
                                const float* __restrict__ bet,
                                fp16* __restrict__ oh, fp16* __restrict__ ol)
{
    int row = blockIdx.x;
    const float* xr = x + (size_t)row * DIMX;
    float s = 0.f, s2 = 0.f;
    for (int c = threadIdx.x; c < DIMX; c += blockDim.x) {
        float v = xr[c];
        s += v; s2 += v * v;
    }
    __shared__ float red[64];
    for (int o = 16; o > 0; o >>= 1) {
        s  += __shfl_xor_sync(0xffffffffu, s,  o);
        s2 += __shfl_xor_sync(0xffffffffu, s2, o);
    }
    int warp = threadIdx.x >> 5, lane = threadIdx.x & 31;
    int nwarp = blockDim.x >> 5;
    if (lane == 0) { red[warp] = s; red[warp + 32] = s2; }
    __syncthreads();
    if (warp == 0) {
        s  = (lane < nwarp) ? red[lane] : 0.f;
        s2 = (lane < nwarp) ? red[lane + 32] : 0.f;
        for (int o = 16; o > 0; o >>= 1) {
            s  += __shfl_xor_sync(0xffffffffu, s,  o);
            s2 += __shfl_xor_sync(0xffffffffu, s2, o);
        }
        if (lane == 0) { red[0] = s; red[1] = s2; }
    }
    __syncthreads();
    float mean = red[0] * (1.f / DIMX);
    float var  = red[1] * (1.f / DIMX) - mean * mean;
    float inv  = rsqrtf(var + 1e-5f);
    for (int c = threadIdx.x; c < DIMX; c += blockDim.x) {
        float y = (xr[c] - mean) * inv * gam[c] + bet[c];
        fp16 h, l; split2h(y, h, l);
        oh[(size_t)row * DIMX + c] = h;
        ol[(size_t)row * DIMX + c] = l;
    }
}

// ---------------- transpose to single fp16 ----------------
__global__ void tsingle_kernel(const float* __restrict__ in, int ldin, long long sIn,
                               fp16* __restrict__ o, int ldout, long long sOut,
                               int R, int C)
{
    __shared__ float t[32][33];
    in += (size_t)blockIdx.z * sIn;
    o  += (size_t)blockIdx.z * sOut;
    int r0 = blockIdx.y * 32, c0 = blockIdx.x * 32;
    int tx = threadIdx.x & 31, ty = threadIdx.x >> 5;
#pragma unroll
    for (int i = 0; i < 32; i += 8) {
        int r = r0 + ty + i;
        if (r < R && c0 + tx < C) t[ty + i][tx] = in[(size_t)r * ldin + c0 + tx];
    }
    __syncthreads();
#pragma unroll
    for (int i = 0; i < 32; i += 8) {
        int c = c0 + ty + i, r = r0 + tx;
        if (c < C && r < R)
            o[(size_t)c * ldout + r] = __float2half_rn(t[tx][ty + i]);
    }
}

// ---------------- remap: q -> hi/lo split, k -> single ----------------
__global__ void remap_split(const float* __restrict__ c12,
                            fp16* __restrict__ qh, fp16* __restrict__ ql,
                            fp16* __restrict__ k)
{
    int idx = blockIdx.x * blockDim.x + threadIdx.x;
    if (idx >= N_TOK * INNER) return;
    int i = idx >> 10, col = idx & 1023;
    int h = col >> 6, d = col & 63;
    float qv = c12[(size_t)i * NQKV + col];
    float kv = c12[(size_t)i * NQKV + INNER + col];
    size_t dst = ((size_t)h * N_TOK + i) * DHEAD + d;
    fp16 a, b;
    split2h(qv, a, b); qh[dst] = a; ql[dst] = b;
    k[dst] = __float2half_rn(kv);
}

// ---------------- fp16 tensor-core GEMM ----------------
// C = alpha * A @ B^T.  128 threads, warp grid (BM/WM) x (BN/WN) = 4 warps.
// ASPLIT: A hi/lo (adds al*b MMA). OCC: min CTAs/SM for launch_bounds.
// MODE 0: C fp32 (+bias). MODE 1: C single fp16. MODE 2: blend with Hm -> fp32.
template<int BM, int BN, int WM, int WN, int ASPLIT, int MODE, int OCC>
__global__ void __launch_bounds__(128, OCC)
gemm_f16(const fp16* __restrict__ Ahi, const fp16* __restrict__ Alo,
         const fp16* __restrict__ Bhi,
         float* __restrict__ C, fp16* __restrict__ Ch,
         const float* __restrict__ Hm,
         int K, int lda, int ldb, int ldc,
         long long sA, long long sB, long long sC,
         float alpha, const float* __restrict__ bias)
{
    constexpr int MI  = WM / 16;
    constexpr int NJ  = WN / 16;
    constexpr int NJ2 = WN / 8;
    constexpr int NAI = BM / 16;
    constexpr int NBI = BN / 16;
    constexpr int ABUF = (ASPLIT ? 2 : 1) * BM * 64;  // halves
    constexpr int BBUF = BN * 64;
    constexpr int SS   = ABUF + BBUF;
    constexpr int WNN = BN / WN;

    extern __shared__ fp16 sm[];

    Ahi += (size_t)blockIdx.z * sA;
    if (ASPLIT) Alo += (size_t)blockIdx.z * sA;
    Bhi += (size_t)blockIdx.z * sB;
    if (MODE == 1) Ch += (size_t)blockIdx.z * sC;
    else           C  += (size_t)blockIdx.z * sC;
    if (MODE == 2) Hm += (size_t)blockIdx.z * sC;

    const int bm = blockIdx.y * BM, bn = blockIdx.x * BN;
    const int tid = threadIdx.x, lane = tid & 31, wid = tid >> 5;
    const int wm0 = (wid / WNN) * WM, wn0 = (wid % WNN) * WN;

    float acc[MI][NJ2][4];
#pragma unroll
    for (int i = 0; i < MI; i++)
#pragma unroll
        for (int j = 0; j < NJ2; j++) {
            acc[i][j][0] = 0.f; acc[i][j][1] = 0.f;
            acc[i][j][2] = 0.f; acc[i][j][3] = 0.f;
        }

    auto issue = [&](int kt, int stg) {
        fp16* sA_hi = sm + stg * SS;
        fp16* sA_lo = sA_hi + BM * 64;
        fp16* sB_hi = sA_hi + ABUF;
#pragma unroll
        for (int i = 0; i < NAI; i++) {
            int id = tid + i * 128, r = id >> 3, c = id & 7;
            size_t go = (size_t)(bm + r) * lda + kt * 64 + c * 8;
            int so = r * 64 + ((c ^ (r & 7)) << 3);
            cp16(s2u(sA_hi + so), Ahi + go);
            if (ASPLIT) cp16(s2u(sA_lo + so), Alo + go);
        }
#pragma unroll
        for (int i = 0; i < NBI; i++) {
            int id = tid + i * 128, r = id >> 3, c = id & 7;
            size_t go = (size_t)(bn + r) * ldb + kt * 64 + c * 8;
            int so = r * 64 + ((c ^ (r & 7)) << 3);
            cp16(s2u(sB_hi + so), Bhi + go);
        }
    };

    const int KT = K >> 6;
    issue(0, 0); cpcommit();

    for (int kt = 0; kt < KT; kt++) {
        int cur = kt & 1;
        if (kt + 1 < KT) { issue(kt + 1, cur ^ 1); cpcommit(); cpwait<1>(); }
        else             { cpwait<0>(); }
        __syncthreads();

        const fp16* sA_hi = sm + cur * SS;
        const fp16* sA_lo = sA_hi + BM * 64;
        const fp16* sB_hi = sA_hi + ABUF;

#pragma unroll
        for (int s = 0; s < 4; s++) {
            const int c0 = 2 * s;
            uint32_t ah[MI][4], al[MI][4];
#pragma unroll
            for (int mi = 0; mi < MI; mi++) {
                int row = wm0 + mi * 16 + (lane & 15);
                int ch  = c0 + (lane >> 4);
                int off = row * 64 + ((ch ^ (row & 7)) << 3);
                ldsm4(ah[mi], s2u(sA_hi + off));
                if (ASPLIT) ldsm4(al[mi], s2u(sA_lo + off));
            }
#pragma unroll
            for (int nj = 0; nj < NJ; nj++) {
                int rowb = wn0 + nj * 16 + (lane & 15);
                int ch   = c0 + (lane >> 4);
                int off  = rowb * 64 + ((ch ^ (rowb & 7)) << 3);
                uint32_t bb[4];
                ldsm4(bb, s2u(sB_hi + off));
#pragma unroll
                for (int mi = 0; mi < MI; mi++) {
                    mma_f16(acc[mi][2 * nj],     ah[mi], bb[0], bb[2]);
                    mma_f16(acc[mi][2 * nj + 1], ah[mi], bb[1], bb[3]);
                    if (ASPLIT) {
                        mma_f16(acc[mi][2 * nj],     al[mi], bb[0], bb[2]);
                        mma_f16(acc[mi][2 * nj + 1], al[mi], bb[1], bb[3]);
                    }
                }
            }
        }
        __syncthreads();
    }

    // ---- epilogue ----
#pragma unroll
    for (int mi = 0; mi < MI; mi++) {
#pragma unroll
        for (int nj2 = 0; nj2 < NJ2; nj2++) {
            int r0  = bm + wm0 + mi * 16 + (lane >> 2);
            int col = bn + wn0 + nj2 * 8 + (lane & 3) * 2;
            float v0 = acc[mi][nj2][0] * alpha, v1 = acc[mi][nj2][1] * alpha;
            float v2 = acc[mi][nj2][2] * alpha, v3 = acc[mi][nj2][3] * alpha;
            size_t o0 = (size_t)r0 * ldc + col;
            size_t o1 = o0 + (size_t)8 * ldc;
            if (MODE == 1) {
                *(__half2*)&Ch[o0] = __halves2half2(__float2half_rn(v0), __float2half_rn(v1));
                *(__half2*)&Ch[o1] = __halves2half2(__float2half_rn(v2), __float2half_rn(v3));
            } else if (MODE == 2) {
                float2 ha = *(const float2*)&Hm[o0];
                float2 hb = *(const float2*)&Hm[o1];
                *(float2*)&C[o0] = make_float2(ALPHA_C * v0 + (1.f - ALPHA_C) * ha.x,
                                               ALPHA_C * v1 + (1.f - ALPHA_C) * ha.y);
                *(float2*)&C[o1] = make_float2(ALPHA_C * v2 + (1.f - ALPHA_C) * hb.x,
                                               ALPHA_C * v3 + (1.f - ALPHA_C) * hb.y);
            } else {
                if (bias) {
                    float b0 = bias[col], b1 = bias[col + 1];
                    v0 += b0; v1 += b1; v2 += b0; v3 += b1;
                }
                *(float2*)&C[o0] = make_float2(v0, v1);
                *(float2*)&C[o1] = make_float2(v2, v3);
            }
        }
    }
}

// ---------------- fused mix_pre + softmax + mix_post ----------------
// Pass A: fp32 float4 mix_pre. Stats: smem-transposed reduction — warp w
// reduces head w. Pass B: probabilities in half2, mix_post via HFMA2.
__global__ void __launch_bounds__(512)
fused_softmax(const float* __restrict__ blended,
              const float* __restrict__ mpre, const float* __restrict__ mpost,
              fp16* __restrict__ at)
{
    extern __shared__ float sd[];                        // [16][2048] mixed dots
    float* redM = sd + HEADS * N_TOK;                    // [16][512]
    float* redL = redM + HEADS * 512;                    // [16][512]
    __shared__ float smixA[HEADS * HEADS];
    __shared__ __half2 smixB2[HEADS * HEADS];
    __shared__ float fm[HEADS], fl[HEADS];

    const int i = blockIdx.x, tid = threadIdx.x;
    const int warp = tid >> 5, lane = tid & 31;
    if (tid < 256) {
        smixA[tid] = mpre[tid];
        smixB2[tid] = __half2half2(__float2half_rn(mpost[tid]));
    }
    __syncthreads();

    const size_t sH = (size_t)N_TOK * N_TOK;
    const size_t hbase = (size_t)i * N_TOK;
    const int j = tid * 4;

    float4 bl4[HEADS];
#pragma unroll
    for (int h = 0; h < HEADS; h++)
        bl4[h] = *(const float4*)&blended[(size_t)h * sH + hbase + j];

    float m[HEADS], l[HEADS];
#pragma unroll
    for (int g = 0; g < HEADS; g++) {
        float4 d = make_float4(0.f, 0.f, 0.f, 0.f);
#pragma unroll
        for (int h = 0; h < HEADS; h++) {
            float w = smixA[h * HEADS + g];
            d.x += bl4[h].x * w; d.y += bl4[h].y * w;
            d.z += bl4[h].z * w; d.w += bl4[h].w * w;
        }
        *(float4*)&sd[g * N_TOK + j] = d;
        float mx = fmaxf(fmaxf(d.x, d.y), fmaxf(d.z, d.w));
        m[g] = mx;
        l[g] = __expf(d.x - mx) + __expf(d.y - mx)
             + __expf(d.z - mx) + __expf(d.w - mx);
    }

    // ---- smem-transposed stats reduction: warp w reduces head w ----
#pragma unroll
    for (int g = 0; g < HEADS; g++) { redM[g * 512 + tid] = m[g]; redL[g * 512 + tid] = l[g]; }
    __syncthreads();
    {
        int g = warp;
        float M = redM[g * 512 + lane], L = redL[g * 512 + lane];
#pragma unroll
        for (int r = 1; r < 16; r++) {
            float m2 = redM[g * 512 + lane + r * 32];
            float l2 = redL[g * 512 + lane + r * 32];
            float nm = fmaxf(M, m2);
            L = L * __expf(M - nm) + l2 * __expf(m2 - nm);
            M = nm;
        }
        for (int o = 16; o > 0; o >>= 1) {
            float m2 = __shfl_xor_sync(0xffffffffu, M, o);
            float l2 = __shfl_xor_sync(0xffffffffu, L, o);
            float nm = fmaxf(M, m2);
            L = L * __expf(M - nm) + l2 * __expf(m2 - nm);
            M = nm;
        }
        if (lane == 0) { fm[g] = M; fl[g] = 1.0f / L; }
    }
    __syncthreads();

    // ---- pass B: p -> half2, mix_post via HFMA2 ----
    __half2 p01[HEADS], p23[HEADS];
#pragma unroll
    for (int h = 0; h < HEADS; h++) {
        float mh = fm[h], li = fl[h];
        float4 d = *(const float4*)&sd[h * N_TOK + j];
        p01[h] = __floats2half2_rn(__expf(d.x - mh) * li, __expf(d.y - mh) * li);
        p23[h] = __floats2half2_rn(__expf(d.z - mh) * li, __expf(d.w - mh) * li);
    }
    const size_t rbase = (size_t)i * (HEADS * N_TOK);
#pragma unroll
    for (int g = 0; g < HEADS; g++) {
        __half2 a01 = __float2half2_rn(0.f), a23 = __float2half2_rn(0.f);
#pragma unroll
        for (int h = 0; h < HEADS; h++) {
            __half2 w2 = smixB2[h * HEADS + g];
            a01 = __hfma2(p01[h], w2, a01);
            a23 = __hfma2(p23[h], w2, a23);
        }
        size_t o = rbase + g * N_TOK + j;
        ((__half2*)&at[o])[0] = a01;
        ((__half2*)&at[o])[1] = a23;
    }
}

// ---------------- launch ----------------
extern "C" void kernel_launch(void* const* d_in, const int* in_sizes, int n_in,
                              void* d_out, int out_size)
{
    const float* x        = (const float*)d_in[0];
    const float* h_in     = (const float*)d_in[1];
    const float* ln_g     = (const float*)d_in[2];
    const float* ln_b     = (const float*)d_in[3];
    const float* Wq       = (const float*)d_in[4];
    const float* Wkv      = (const float*)d_in[5];
    const float* mix_pre  = (const float*)d_in[6];
    const float* mix_post = (const float*)d_in[7];
    const float* Wout     = (const float*)d_in[8];
    const float* bout     = (const float*)d_in[9];

    float* out = (float*)d_out;
    float* blended_out = out + (size_t)N_TOK * DIMX;

    float* c12;
    fp16 *xnh, *xnl, *wqkv, *wo, *qh, *ql, *k, *vt, *at, *ao;
    cudaGetSymbolAddress((void**)&c12,  g_c12);
    cudaGetSymbolAddress((void**)&xnh,  g_xnh);
    cudaGetSymbolAddress((void**)&xnl,  g_xnl);
    cudaGetSymbolAddress((void**)&wqkv, g_wqkv);
    cudaGetSymbolAddress((void**)&wo,   g_wo);
    cudaGetSymbolAddress((void**)&qh,   g_qh);
    cudaGetSymbolAddress((void**)&ql,   g_ql);
    cudaGetSymbolAddress((void**)&k,    g_k);
    cudaGetSymbolAddress((void**)&vt,   g_vt);
    cudaGetSymbolAddress((void**)&at,   g_at);
    cudaGetSymbolAddress((void**)&ao,   g_ao);

    // smem sizes (bytes)
    const int SM_QKV = 2 * (2 * 128 + 128) * 128;   // 98304 (A split, 2 stg)
    const int SM_QK  = (2 * 128 + 64) * 128;        // 40960 (A split, BN=64, 1 stg)
    const int SM_AV  = 2 * (128 + 64) * 128;        // 49152 (no split, 2 stg)
    const int SM_SOFT = HEADS * N_TOK * 4 + 2 * HEADS * 512 * 4;  // 196608
    cudaFuncSetAttribute(gemm_f16<128, 128, 64, 64, 1, 0, 2>,
                         cudaFuncAttributeMaxDynamicSharedMemorySize, SM_QKV);
    cudaFuncSetAttribute(gemm_f16<128, 64, 64, 32, 1, 2, 3>,
                         cudaFuncAttributeMaxDynamicSharedMemorySize, SM_QK);
    cudaFuncSetAttribute(gemm_f16<128, 64, 64, 32, 0, 1, 2>,
                         cudaFuncAttributeMaxDynamicSharedMemorySize, SM_AV);
    cudaFuncSetAttribute(gemm_f16<128, 64, 64, 32, 0, 0, 2>,
                         cudaFuncAttributeMaxDynamicSharedMemorySize, SM_AV);
    cudaFuncSetAttribute(fused_softmax,
                         cudaFuncAttributeMaxDynamicSharedMemorySize, SM_SOFT);

    // 1. layernorm + fp16 split
    ln_split_kernel<<<N_TOK, 256>>>(x, ln_g, ln_b, xnh, xnl);

    // 2. weight transposes -> single fp16 K-major
    tsingle_kernel<<<dim3(32, 32, 1), 256>>>(Wq, INNER, 0, wqkv, DIMX, 0, DIMX, INNER);
    tsingle_kernel<<<dim3(64, 32, 1), 256>>>(Wkv, 2 * INNER, 0,
                                             wqkv + (size_t)INNER * DIMX, DIMX, 0,
                                             DIMX, 2 * INNER);
    tsingle_kernel<<<dim3(32, 32, 1), 256>>>(Wout, DIMX, 0, wo, INNER, 0, INNER, DIMX);

    // 3. c12 = xn @ [Wq|Wkv]  (M=2048, N=3072, K=1024)  A-split 2-MMA
    gemm_f16<128, 128, 64, 64, 1, 0, 2><<<dim3(NQKV / 128, N_TOK / 128, 1), 128, SM_QKV>>>(
        xnh, xnl, wqkv, c12, nullptr, nullptr,
        DIMX, DIMX, DIMX, NQKV, 0, 0, 0, 1.f, nullptr);

    // 4. remap q hi/lo, k single; 5. v^T single
    remap_split<<<(N_TOK * INNER + 255) / 256, 256>>>(c12, qh, ql, k);
    tsingle_kernel<<<dim3(2, 64, HEADS), 256>>>(c12 + 2 * INNER, NQKV, DHEAD,
                                                vt, N_TOK, (long long)DHEAD * N_TOK,
                                                N_TOK, DHEAD);

    // 6. blended[h][i][j] = 0.45*SCALE*(q@k^T) + 0.55*h  (BN=64, 3 CTAs/SM)
    gemm_f16<128, 64, 64, 32, 1, 2, 3><<<dim3(N_TOK / 64, N_TOK / 128, HEADS), 128, SM_QK>>>(
        qh, ql, k, blended_out, nullptr, h_in,
        DHEAD, DHEAD, DHEAD, N_TOK,
        (long long)N_TOK * DHEAD, (long long)N_TOK * DHEAD,
        (long long)N_TOK * N_TOK,
        SCALE_C, nullptr);

    // 7. fused mix_pre + softmax + mix_post -> attn single fp16 [i][g][j]
    fused_softmax<<<N_TOK, 512, SM_SOFT>>>(blended_out, mix_pre, mix_post, at);

    // 8. ao = attn @ v  (per head; M=2048, N=64, K=2048) 1-MMA -> single fp16
    gemm_f16<128, 64, 64, 32, 0, 1, 2><<<dim3(1, N_TOK / 128, HEADS), 128, SM_AV>>>(
        at, nullptr, vt, nullptr, ao, nullptr,
        N_TOK, HEADS * N_TOK, N_TOK, INNER,
        (long long)N_TOK, (long long)DHEAD * N_TOK, (long long)DHEAD,
        1.f, nullptr);

    // 9. out = ao @ Wout + bout  (M=2048, N=1024, K=1024) 1-MMA, BN=64
    gemm_f16<128, 64, 64, 32, 0, 0, 2><<<dim3(DIMX / 64, N_TOK / 128, 1), 128, SM_AV>>>(
        ao, nullptr, wo, out, nullptr, nullptr,
        INNER, INNER, INNER, DIMX, 0, 0, 0, 1.f, bout);

    (void)in_sizes; (void)n_in; (void)out_size;
}

// round 16
// speedup vs baseline: 1.1675x; 1.0219x over previous
#include <cuda_runtime.h>
#include <cuda_fp16.h>
#include <math.h>
#include <stdint.h>

#define N_TOK 2048
#define DIMX  1024
#define HEADS 16
#define DHEAD 64
#define INNER 1024
#define NQKV  3072
#define ALPHA_C 0.45f
#define SCALE_C 0.125f

typedef __half fp16;

// ---------------- device buffers ----------------
__device__ __align__(256) float g_c12[(size_t)N_TOK * 2 * INNER];   // q,k fp32
__device__ __align__(256) fp16  g_v16[(size_t)N_TOK * INNER];       // v fp16
__device__ __align__(256) fp16  g_xnh[(size_t)N_TOK * DIMX];
__device__ __align__(256) fp16  g_xnl[(size_t)N_TOK * DIMX];
__device__ __align__(256) fp16  g_wqkv[(size_t)NQKV * DIMX];
__device__ __align__(256) fp16  g_wo[(size_t)DIMX * INNER];
__device__ __align__(256) fp16  g_qh[(size_t)HEADS * N_TOK * DHEAD];
__device__ __align__(256) fp16  g_ql[(size_t)HEADS * N_TOK * DHEAD];
__device__ __align__(256) fp16  g_k[(size_t)HEADS * N_TOK * DHEAD];
__device__ __align__(256) fp16  g_vt[(size_t)HEADS * DHEAD * N_TOK];
__device__ __align__(256) fp16  g_at[(size_t)HEADS * N_TOK * N_TOK];  // [i][g][j]
__device__ __align__(256) fp16  g_ao[(size_t)N_TOK * INNER];

// ---------------- helpers ----------------
__device__ __forceinline__ uint32_t s2u(const void* p) {
    return (uint32_t)__cvta_generic_to_shared(p);
}
__device__ __forceinline__ void cp16(uint32_t d, const void* g) {
    asm volatile("cp.async.cg.shared.global [%0],[%1],16;" :: "r"(d), "l"(g));
}
__device__ __forceinline__ void cpcommit() { asm volatile("cp.async.commit_group;"); }
template<int Nw> __device__ __forceinline__ void cpwait() {
    asm volatile("cp.async.wait_group %0;" :: "n"(Nw));
}
__device__ __forceinline__ void ldsm4(uint32_t* r, uint32_t addr) {
    asm volatile("ldmatrix.sync.aligned.m8n8.x4.shared.b16 {%0,%1,%2,%3},[%4];"
                 : "=r"(r[0]), "=r"(r[1]), "=r"(r[2]), "=r"(r[3]) : "r"(addr));
}
__device__ __forceinline__ void mma_f16(float* d, const uint32_t* a, uint32_t b0, uint32_t b1) {
    asm volatile(
        "mma.sync.aligned.m16n8k16.row.col.f32.f16.f16.f32 "
        "{%0,%1,%2,%3},{%4,%5,%6,%7},{%8,%9},{%0,%1,%2,%3};"
        : "+f"(d[0]), "+f"(d[1]), "+f"(d[2]), "+f"(d[3])
        : "r"(a[0]), "r"(a[1]), "r"(a[2]), "r"(a[3]), "r"(b0), "r"(b1));
}
__device__ __forceinline__ void split2h(float v, fp16& h, fp16& l) {
    h = __float2half_rn(v);
    l = __float2half_rn(v - __half2float(h));
}

// ---------------- layernorm + fp16 hi/lo split ----------------
__global__ void ln_split_kernel(const float* __restrict__ x,
                                const float* __restrict__ gam,
                                const float* __restrict__ bet,
                                fp16* __restrict__ oh, fp16* __restrict__ ol)
{
    int row = blockIdx.x;
    const float* xr = x + (size_t)row * DIMX;
    float s = 0.f, s2 = 0.f;
    for (int c = threadIdx.x; c < DIMX; c += blockDim.x) {
        float v = xr[c];
        s += v; s2 += v * v;
    }
    __shared__ float red[64];
    for (int o = 16; o > 0; o >>= 1) {
        s  += __shfl_xor_sync(0xffffffffu, s,  o);
        s2 += __shfl_xor_sync(0xffffffffu, s2, o);
    }
    int warp = threadIdx.x >> 5, lane = threadIdx.x & 31;
    int nwarp = blockDim.x >> 5;
    if (lane == 0) { red[warp] = s; red[warp + 32] = s2; }
    __syncthreads();
    if (warp == 0) {
        s  = (lane < nwarp) ? red[lane] : 0.f;
        s2 = (lane < nwarp) ? red[lane + 32] : 0.f;
        for (int o = 16; o > 0; o >>= 1) {
            s  += __shfl_xor_sync(0xffffffffu, s,  o);
            s2 += __shfl_xor_sync(0xffffffffu, s2, o);
        }
        if (lane == 0) { red[0] = s; red[1] = s2; }
    }
    __syncthreads();
    float mean = red[0] * (1.f / DIMX);
    float var  = red[1] * (1.f / DIMX) - mean * mean;
    float inv  = rsqrtf(var + 1e-5f);
    for (int c = threadIdx.x; c < DIMX; c += blockDim.x) {
        float y = (xr[c] - mean) * inv * gam[c] + bet[c];
        fp16 h, l; split2h(y, h, l);
        oh[(size_t)row * DIMX + c] = h;
        ol[(size_t)row * DIMX + c] = l;
    }
}

// ---------------- transpose fp32 -> single fp16 ----------------
__global__ void tsingle_kernel(const float* __restrict__ in, int ldin, long long sIn,
                               fp16* __restrict__ o, int ldout, long long sOut,
                               int R, int C)
{
    __shared__ float t[32][33];
    in += (size_t)blockIdx.z * sIn;
    o  += (size_t)blockIdx.z * sOut;
    int r0 = blockIdx.y * 32, c0 = blockIdx.x * 32;
    int tx = threadIdx.x & 31, ty = threadIdx.x >> 5;
#pragma unroll
    for (int i = 0; i < 32; i += 8) {
        int r = r0 + ty + i;
        if (r < R && c0 + tx < C) t[ty + i][tx] = in[(size_t)r * ldin + c0 + tx];
    }
    __syncthreads();
#pragma unroll
    for (int i = 0; i < 32; i += 8) {
        int c = c0 + ty + i, r = r0 + tx;
        if (c < C && r < R)
            o[(size_t)c * ldout + r] = __float2half_rn(t[tx][ty + i]);
    }
}

// ---------------- transpose fp16 -> fp16 ----------------
__global__ void t16_kernel(const fp16* __restrict__ in, int ldin, long long sIn,
                           fp16* __restrict__ o, int ldout, long long sOut,
                           int R, int C)
{
    __shared__ fp16 t[32][34];
    in += (size_t)blockIdx.z * sIn;
    o  += (size_t)blockIdx.z * sOut;
    int r0 = blockIdx.y * 32, c0 = blockIdx.x * 32;
    int tx = threadIdx.x & 31, ty = threadIdx.x >> 5;
#pragma unroll
    for (int i = 0; i < 32; i += 8) {
        int r = r0 + ty + i;
        if (r < R && c0 + tx < C) t[ty + i][tx] = in[(size_t)r * ldin + c0 + tx];
    }
    __syncthreads();
#pragma unroll
    for (int i = 0; i < 32; i += 8) {
        int c = c0 + ty + i, r = r0 + tx;
        if (c < C && r < R)
            o[(size_t)c * ldout + r] = t[tx][ty + i];
    }
}

// ---------------- remap: q -> hi/lo split, k -> single (c12 ld = 2048) ----------------
__global__ void remap_split(const float* __restrict__ c12,
                            fp16* __restrict__ qh, fp16* __restrict__ ql,
                            fp16* __restrict__ k)
{
    int idx = blockIdx.x * blockDim.x + threadIdx.x;
    if (idx >= N_TOK * INNER) return;
    int i = idx >> 10, col = idx & 1023;
    int h = col >> 6, d = col & 63;
    float qv = c12[(size_t)i * (2 * INNER) + col];
    float kv = c12[(size_t)i * (2 * INNER) + INNER + col];
    size_t dst = ((size_t)h * N_TOK + i) * DHEAD + d;
    fp16 a, b;
    split2h(qv, a, b); qh[dst] = a; ql[dst] = b;
    k[dst] = __float2half_rn(kv);
}

// ---------------- fp16 tensor-core GEMM ----------------
// C = alpha * A @ B^T.  128 threads, warp grid (BM/WM) x (BN/WN) = 4 warps.
// ASPLIT: A hi/lo (adds al*b MMA). OCC: min CTAs/SM for launch_bounds.
// MODE 0: C fp32 (+bias). MODE 1: C single fp16. MODE 2: blend with Hm -> fp32.
template<int BM, int BN, int WM, int WN, int ASPLIT, int MODE, int OCC>
__global__ void __launch_bounds__(128, OCC)
gemm_f16(const fp16* __restrict__ Ahi, const fp16* __restrict__ Alo,
         const fp16* __restrict__ Bhi,
         float* __restrict__ C, fp16* __restrict__ Ch,
         const float* __restrict__ Hm,
         int K, int lda, int ldb, int ldc,
         long long sA, long long sB, long long sC,
         float alpha, const float* __restrict__ bias)
{
    constexpr int MI  = WM / 16;
    constexpr int NJ  = WN / 16;
    constexpr int NJ2 = WN / 8;
    constexpr int NAI = BM / 16;
    constexpr int NBI = BN / 16;
    constexpr int ABUF = (ASPLIT ? 2 : 1) * BM * 64;  // halves
    constexpr int BBUF = BN * 64;
    constexpr int SS   = ABUF + BBUF;
    constexpr int WNN = BN / WN;

    extern __shared__ fp16 sm[];

    Ahi += (size_t)blockIdx.z * sA;
    if (ASPLIT) Alo += (size_t)blockIdx.z * sA;
    Bhi += (size_t)blockIdx.z * sB;
    if (MODE == 1) Ch += (size_t)blockIdx.z * sC;
    else           C  += (size_t)blockIdx.z * sC;
    if (MODE == 2) Hm += (size_t)blockIdx.z * sC;

    const int bm = blockIdx.y * BM, bn = blockIdx.x * BN;
    const int tid = threadIdx.x, lane = tid & 31, wid = tid >> 5;
    const int wm0 = (wid / WNN) * WM, wn0 = (wid % WNN) * WN;

    float acc[MI][NJ2][4];
#pragma unroll
    for (int i = 0; i < MI; i++)
#pragma unroll
        for (int j = 0; j < NJ2; j++) {
            acc[i][j][0] = 0.f; acc[i][j][1] = 0.f;
            acc[i][j][2] = 0.f; acc[i][j][3] = 0.f;
        }

    auto issue = [&](int kt, int stg) {
        fp16* sA_hi = sm + stg * SS;
        fp16* sA_lo = sA_hi + BM * 64;
        fp16* sB_hi = sA_hi + ABUF;
#pragma unroll
        for (int i = 0; i < NAI; i++) {
            int id = tid + i * 128, r = id >> 3, c = id & 7;
            size_t go = (size_t)(bm + r) * lda + kt * 64 + c * 8;
            int so = r * 64 + ((c ^ (r & 7)) << 3);
            cp16(s2u(sA_hi + so), Ahi + go);
            if (ASPLIT) cp16(s2u(sA_lo + so), Alo + go);
        }
#pragma unroll
        for (int i = 0; i < NBI; i++) {
            int id = tid + i * 128, r = id >> 3, c = id & 7;
            size_t go = (size_t)(bn + r) * ldb + kt * 64 + c * 8;
            int so = r * 64 + ((c ^ (r & 7)) << 3);
            cp16(s2u(sB_hi + so), Bhi + go);
        }
    };

    const int KT = K >> 6;
    issue(0, 0); cpcommit();

    for (int kt = 0; kt < KT; kt++) {
        int cur = kt & 1;
        if (kt + 1 < KT) { issue(kt + 1, cur ^ 1); cpcommit(); cpwait<1>(); }
        else             { cpwait<0>(); }
        __syncthreads();

        const fp16* sA_hi = sm + cur * SS;
        const fp16* sA_lo = sA_hi + BM * 64;
        const fp16* sB_hi = sA_hi + ABUF;

#pragma unroll
        for (int s = 0; s < 4; s++) {
            const int c0 = 2 * s;
            uint32_t ah[MI][4], al[MI][4];
#pragma unroll
            for (int mi = 0; mi < MI; mi++) {
                int row = wm0 + mi * 16 + (lane & 15);
                int ch  = c0 + (lane >> 4);
                int off = row * 64 + ((ch ^ (row & 7)) << 3);
                ldsm4(ah[mi], s2u(sA_hi + off));
                if (ASPLIT) ldsm4(al[mi], s2u(sA_lo + off));
            }
#pragma unroll
            for (int nj = 0; nj < NJ; nj++) {
                int rowb = wn0 + nj * 16 + (lane & 15);
                int ch   = c0 + (lane >> 4);
                int off  = rowb * 64 + ((ch ^ (rowb & 7)) << 3);
                uint32_t bb[4];
                ldsm4(bb, s2u(sB_hi + off));
#pragma unroll
                for (int mi = 0; mi < MI; mi++) {
                    mma_f16(acc[mi][2 * nj],     ah[mi], bb[0], bb[2]);
                    mma_f16(acc[mi][2 * nj + 1], ah[mi], bb[1], bb[3]);
                    if (ASPLIT) {
                        mma_f16(acc[mi][2 * nj],     al[mi], bb[0], bb[2]);
                        mma_f16(acc[mi][2 * nj + 1], al[mi], bb[1], bb[3]);
                    }
                }
            }
        }
        __syncthreads();
    }

    // ---- epilogue ----
#pragma unroll
    for (int mi = 0; mi < MI; mi++) {
#pragma unroll
        for (int nj2 = 0; nj2 < NJ2; nj2++) {
            int r0  = bm + wm0 + mi * 16 + (lane >> 2);
            int col = bn + wn0 + nj2 * 8 + (lane & 3) * 2;
            float v0 = acc[mi][nj2][0] * alpha, v1 = acc[mi][nj2][1] * alpha;
            float v2 = acc[mi][nj2][2] * alpha, v3 = acc[mi][nj2][3] * alpha;
            size_t o0 = (size_t)r0 * ldc + col;
            size_t o1 = o0 + (size_t)8 * ldc;
            if (MODE == 1) {
                *(__half2*)&Ch[o0] = __halves2half2(__float2half_rn(v0), __float2half_rn(v1));
                *(__half2*)&Ch[o1] = __halves2half2(__float2half_rn(v2), __float2half_rn(v3));
            } else if (MODE == 2) {
                float2 ha = *(const float2*)&Hm[o0];
                float2 hb = *(const float2*)&Hm[o1];
                *(float2*)&C[o0] = make_float2(ALPHA_C * v0 + (1.f - ALPHA_C) * ha.x,
                                               ALPHA_C * v1 + (1.f - ALPHA_C) * ha.y);
                *(float2*)&C[o1] = make_float2(ALPHA_C * v2 + (1.f - ALPHA_C) * hb.x,
                                               ALPHA_C * v3 + (1.f - ALPHA_C) * hb.y);
            } else {
                if (bias) {
                    float b0 = bias[col], b1 = bias[col + 1];
                    v0 += b0; v1 += b1; v2 += b0; v3 += b1;
                }
                *(float2*)&C[o0] = make_float2(v0, v1);
                *(float2*)&C[o1] = make_float2(v2, v3);
            }
        }
    }
}

// ---------------- fused mix_pre + softmax + mix_post ----------------
__global__ void __launch_bounds__(512)
fused_softmax(const float* __restrict__ blended,
              const float* __restrict__ mpre, const float* __restrict__ mpost,
              fp16* __restrict__ at)
{
    extern __shared__ float sd[];                        // [16][2048] mixed dots
    float* redM = sd + HEADS * N_TOK;                    // [16][512]
    float* redL = redM + HEADS * 512;                    // [16][512]
    __shared__ float smixA[HEADS * HEADS];
    __shared__ __half2 smixB2[HEADS * HEADS];
    __shared__ float fm[HEADS], fl[HEADS];

    const int i = blockIdx.x, tid = threadIdx.x;
    const int warp = tid >> 5, lane = tid & 31;
    if (tid < 256) {
        smixA[tid] = mpre[tid];
        smixB2[tid] = __half2half2(__float2half_rn(mpost[tid]));
    }
    __syncthreads();

    const size_t sH = (size_t)N_TOK * N_TOK;
    const size_t hbase = (size_t)i * N_TOK;
    const int j = tid * 4;

    float4 bl4[HEADS];
#pragma unroll
    for (int h = 0; h < HEADS; h++)
        bl4[h] = *(const float4*)&blended[(size_t)h * sH + hbase + j];

    float m[HEADS], l[HEADS];
#pragma unroll
    for (int g = 0; g < HEADS; g++) {
        float4 d = make_float4(0.f, 0.f, 0.f, 0.f);
#pragma unroll
        for (int h = 0; h < HEADS; h++) {
            float w = smixA[h * HEADS + g];
            d.x += bl4[h].x * w; d.y += bl4[h].y * w;
            d.z += bl4[h].z * w; d.w += bl4[h].w * w;
        }
        *(float4*)&sd[g * N_TOK + j] = d;
        float mx = fmaxf(fmaxf(d.x, d.y), fmaxf(d.z, d.w));
        m[g] = mx;
        l[g] = __expf(d.x - mx) + __expf(d.y - mx)
             + __expf(d.z - mx) + __expf(d.w - mx);
    }

#pragma unroll
    for (int g = 0; g < HEADS; g++) { redM[g * 512 + tid] = m[g]; redL[g * 512 + tid] = l[g]; }
    __syncthreads();
    {
        int g = warp;
        float M = redM[g * 512 + lane], L = redL[g * 512 + lane];
#pragma unroll
        for (int r = 1; r < 16; r++) {
            float m2 = redM[g * 512 + lane + r * 32];
            float l2 = redL[g * 512 + lane + r * 32];
            float nm = fmaxf(M, m2);
            L = L * __expf(M - nm) + l2 * __expf(m2 - nm);
            M = nm;
        }
        for (int o = 16; o > 0; o >>= 1) {
            float m2 = __shfl_xor_sync(0xffffffffu, M, o);
            float l2 = __shfl_xor_sync(0xffffffffu, L, o);
            float nm = fmaxf(M, m2);
            L = L * __expf(M - nm) + l2 * __expf(m2 - nm);
            M = nm;
        }
        if (lane == 0) { fm[g] = M; fl[g] = 1.0f / L; }
    }
    __syncthreads();

    __half2 p01[HEADS], p23[HEADS];
#pragma unroll
    for (int h = 0; h < HEADS; h++) {
        float mh = fm[h], li = fl[h];
        float4 d = *(const float4*)&sd[h * N_TOK + j];
        p01[h] = __floats2half2_rn(__expf(d.x - mh) * li, __expf(d.y - mh) * li);
        p23[h] = __floats2half2_rn(__expf(d.z - mh) * li, __expf(d.w - mh) * li);
    }
    const size_t rbase = (size_t)i * (HEADS * N_TOK);
#pragma unroll
    for (int g = 0; g < HEADS; g++) {
        __half2 a01 = __float2half2_rn(0.f), a23 = __float2half2_rn(0.f);
#pragma unroll
        for (int h = 0; h < HEADS; h++) {
            __half2 w2 = smixB2[h * HEADS + g];
            a01 = __hfma2(p01[h], w2, a01);
            a23 = __hfma2(p23[h], w2, a23);
        }
        size_t o = rbase + g * N_TOK + j;
        ((__half2*)&at[o])[0] = a01;
        ((__half2*)&at[o])[1] = a23;
    }
}

// ---------------- launch ----------------
extern "C" void kernel_launch(void* const* d_in, const int* in_sizes, int n_in,
                              void* d_out, int out_size)
{
    const float* x        = (const float*)d_in[0];
    const float* h_in     = (const float*)d_in[1];
    const float* ln_g     = (const float*)d_in[2];
    const float* ln_b     = (const float*)d_in[3];
    const float* Wq       = (const float*)d_in[4];
    const float* Wkv      = (const float*)d_in[5];
    const float* mix_pre  = (const float*)d_in[6];
    const float* mix_post = (const float*)d_in[7];
    const float* Wout     = (const float*)d_in[8];
    const float* bout     = (const float*)d_in[9];

    float* out = (float*)d_out;
    float* blended_out = out + (size_t)N_TOK * DIMX;

    float* c12;
    fp16 *v16, *xnh, *xnl, *wqkv, *wo, *qh, *ql, *k, *vt, *at, *ao;
    cudaGetSymbolAddress((void**)&c12,  g_c12);
    cudaGetSymbolAddress((void**)&v16,  g_v16);
    cudaGetSymbolAddress((void**)&xnh,  g_xnh);
    cudaGetSymbolAddress((void**)&xnl,  g_xnl);
    cudaGetSymbolAddress((void**)&wqkv, g_wqkv);
    cudaGetSymbolAddress((void**)&wo,   g_wo);
    cudaGetSymbolAddress((void**)&qh,   g_qh);
    cudaGetSymbolAddress((void**)&ql,   g_ql);
    cudaGetSymbolAddress((void**)&k,    g_k);
    cudaGetSymbolAddress((void**)&vt,   g_vt);
    cudaGetSymbolAddress((void**)&at,   g_at);
    cudaGetSymbolAddress((void**)&ao,   g_ao);

    // smem sizes (bytes)
    const int SM_QKV = 2 * (2 * 128 + 128) * 128;   // 98304 (A split, 2 stg)
    const int SM_QK  = (2 * 128 + 64) * 128;        // 40960 (A split, BN=64, 1 stg)
    const int SM_AV  = 2 * (128 + 64) * 128;        // 49152 (no split, 2 stg)
    const int SM_SOFT = HEADS * N_TOK * 4 + 2 * HEADS * 512 * 4;  // 196608
    cudaFuncSetAttribute(gemm_f16<128, 128, 64, 64, 1, 0, 2>,
                         cudaFuncAttributeMaxDynamicSharedMemorySize, SM_QKV);
    cudaFuncSetAttribute(gemm_f16<128, 64, 64, 32, 1, 2, 3>,
                         cudaFuncAttributeMaxDynamicSharedMemorySize, SM_QK);
    cudaFuncSetAttribute(gemm_f16<128, 64, 64, 32, 0, 1, 2>,
                         cudaFuncAttributeMaxDynamicSharedMemorySize, SM_AV);
    cudaFuncSetAttribute(gemm_f16<128, 64, 64, 32, 0, 0, 2>,
                         cudaFuncAttributeMaxDynamicSharedMemorySize, SM_AV);
    cudaFuncSetAttribute(fused_softmax,
                         cudaFuncAttributeMaxDynamicSharedMemorySize, SM_SOFT);

    // 1. layernorm + fp16 split
    ln_split_kernel<<<N_TOK, 256>>>(x, ln_g, ln_b, xnh, xnl);

    // 2. weight transposes -> single fp16 K-major
    tsingle_kernel<<<dim3(32, 32, 1), 256>>>(Wq, INNER, 0, wqkv, DIMX, 0, DIMX, INNER);
    tsingle_kernel<<<dim3(64, 32, 1), 256>>>(Wkv, 2 * INNER, 0,
                                             wqkv + (size_t)INNER * DIMX, DIMX, 0,
                                             DIMX, 2 * INNER);
    tsingle_kernel<<<dim3(32, 32, 1), 256>>>(Wout, DIMX, 0, wo, INNER, 0, INNER, DIMX);

    // 3a. c12 = xn @ [Wq|Wk]  (M=2048, N=2048, K=1024)  A-split 2-MMA, ldc=2048
    gemm_f16<128, 128, 64, 64, 1, 0, 2><<<dim3(2 * INNER / 128, N_TOK / 128, 1), 128, SM_QKV>>>(
        xnh, xnl, wqkv, c12, nullptr, nullptr,
        DIMX, DIMX, DIMX, 2 * INNER, 0, 0, 0, 1.f, nullptr);

    // 3b. v16 = xnh @ Wv  (M=2048, N=1024, K=1024)  1-MMA -> fp16 direct
    gemm_f16<128, 64, 64, 32, 0, 1, 2><<<dim3(INNER / 64, N_TOK / 128, 1), 128, SM_AV>>>(
        xnh, nullptr, wqkv + (size_t)(2 * INNER) * DIMX, nullptr, v16, nullptr,
        DIMX, DIMX, DIMX, INNER, 0, 0, 0, 1.f, nullptr);

    // 4. remap q hi/lo, k single; 5. v^T (fp16 -> fp16 transpose)
    remap_split<<<(N_TOK * INNER + 255) / 256, 256>>>(c12, qh, ql, k);
    t16_kernel<<<dim3(2, 64, HEADS), 256>>>(v16, INNER, DHEAD,
                                            vt, N_TOK, (long long)DHEAD * N_TOK,
                                            N_TOK, DHEAD);

    // 6. blended[h][i][j] = 0.45*SCALE*(q@k^T) + 0.55*h  (BN=64, 3 CTAs/SM)
    gemm_f16<128, 64, 64, 32, 1, 2, 3><<<dim3(N_TOK / 64, N_TOK / 128, HEADS), 128, SM_QK>>>(
        qh, ql, k, blended_out, nullptr, h_in,
        DHEAD, DHEAD, DHEAD, N_TOK,
        (long long)N_TOK * DHEAD, (long long)N_TOK * DHEAD,
        (long long)N_TOK * N_TOK,
        SCALE_C, nullptr);

    // 7. fused mix_pre + softmax + mix_post -> attn single fp16 [i][g][j]
    fused_softmax<<<N_TOK, 512, SM_SOFT>>>(blended_out, mix_pre, mix_post, at);

    // 8. ao = attn @ v  (per head; M=2048, N=64, K=2048) 1-MMA -> single fp16
    gemm_f16<128, 64, 64, 32, 0, 1, 2><<<dim3(1, N_TOK / 128, HEADS), 128, SM_AV>>>(
        at, nullptr, vt, nullptr, ao, nullptr,
        N_TOK, HEADS * N_TOK, N_TOK, INNER,
        (long long)N_TOK, (long long)DHEAD * N_TOK, (long long)DHEAD,
        1.f, nullptr);

    // 9. out = ao @ Wout + bout  (M=2048, N=1024, K=1024) 1-MMA, BN=64
    gemm_f16<128, 64, 64, 32, 0, 0, 2><<<dim3(DIMX / 64, N_TOK / 128, 1), 128, SM_AV>>>(
        ao, nullptr, wo, out, nullptr, nullptr,
        INNER, INNER, INNER, DIMX, 0, 0, 0, 1.f, bout);

    (void)in_sizes; (void)n_in; (void)out_size;
}

// round 17
// speedup vs baseline: 1.1810x; 1.0115x over previous
#include <cuda_runtime.h>
#include <cuda_fp16.h>
#include <math.h>
#include <stdint.h>

#define N_TOK 2048
#define DIMX  1024
#define HEADS 16
#define DHEAD 64
#define INNER 1024
#define NQKV  3072
#define ALPHA_C 0.45f
#define SCALE_C 0.125f

typedef __half fp16;

// ---------------- device buffers ----------------
__device__ __align__(256) fp16  g_v16[(size_t)N_TOK * INNER];       // v fp16
__device__ __align__(256) fp16  g_xnh[(size_t)N_TOK * DIMX];
__device__ __align__(256) fp16  g_xnl[(size_t)N_TOK * DIMX];
__device__ __align__(256) fp16  g_wqkv[(size_t)NQKV * DIMX];
__device__ __align__(256) fp16  g_wo[(size_t)DIMX * INNER];
__device__ __align__(256) fp16  g_qh[(size_t)HEADS * N_TOK * DHEAD];
__device__ __align__(256) fp16  g_ql[(size_t)HEADS * N_TOK * DHEAD];
__device__ __align__(256) fp16  g_k[(size_t)HEADS * N_TOK * DHEAD];
__device__ __align__(256) fp16  g_vt[(size_t)HEADS * DHEAD * N_TOK];
__device__ __align__(256) fp16  g_at[(size_t)HEADS * N_TOK * N_TOK];  // [i][g][j]
__device__ __align__(256) fp16  g_ao[(size_t)N_TOK * INNER];

// ---------------- helpers ----------------
__device__ __forceinline__ uint32_t s2u(const void* p) {
    return (uint32_t)__cvta_generic_to_shared(p);
}
__device__ __forceinline__ void cp16(uint32_t d, const void* g) {
    asm volatile("cp.async.cg.shared.global [%0],[%1],16;" :: "r"(d), "l"(g));
}
__device__ __forceinline__ void cpcommit() { asm volatile("cp.async.commit_group;"); }
template<int Nw> __device__ __forceinline__ void cpwait() {
    asm volatile("cp.async.wait_group %0;" :: "n"(Nw));
}
__device__ __forceinline__ void ldsm4(uint32_t* r, uint32_t addr) {
    asm volatile("ldmatrix.sync.aligned.m8n8.x4.shared.b16 {%0,%1,%2,%3},[%4];"
                 : "=r"(r[0]), "=r"(r[1]), "=r"(r[2]), "=r"(r[3]) : "r"(addr));
}
__device__ __forceinline__ void mma_f16(float* d, const uint32_t* a, uint32_t b0, uint32_t b1) {
    asm volatile(
        "mma.sync.aligned.m16n8k16.row.col.f32.f16.f16.f32 "
        "{%0,%1,%2,%3},{%4,%5,%6,%7},{%8,%9},{%0,%1,%2,%3};"
        : "+f"(d[0]), "+f"(d[1]), "+f"(d[2]), "+f"(d[3])
        : "r"(a[0]), "r"(a[1]), "r"(a[2]), "r"(a[3]), "r"(b0), "r"(b1));
}
__device__ __forceinline__ void split2h(float v, fp16& h, fp16& l) {
    h = __float2half_rn(v);
    l = __float2half_rn(v - __half2float(h));
}

// ---------------- layernorm + fp16 hi/lo split ----------------
__global__ void ln_split_kernel(const float* __restrict__ x,
                                const float* __restrict__ gam,
                                const float* __restrict__ bet,
                                fp16* __restrict__ oh, fp16* __restrict__ ol)
{
    int row = blockIdx.x;
    const float* xr = x + (size_t)row * DIMX;
    float s = 0.f, s2 = 0.f;
    for (int c = threadIdx.x; c < DIMX; c += blockDim.x) {
        float v = xr[c];
        s += v; s2 += v * v;
    }
    __shared__ float red[64];
    for (int o = 16; o > 0; o >>= 1) {
        s  += __shfl_xor_sync(0xffffffffu, s,  o);
        s2 += __shfl_xor_sync(0xffffffffu, s2, o);
    }
    int warp = threadIdx.x >> 5, lane = threadIdx.x & 31;
    int nwarp = blockDim.x >> 5;
    if (lane == 0) { red[warp] = s; red[warp + 32] = s2; }
    __syncthreads();
    if (warp == 0) {
        s  = (lane < nwarp) ? red[lane] : 0.f;
        s2 = (lane < nwarp) ? red[lane + 32] : 0.f;
        for (int o = 16; o > 0; o >>= 1) {
            s  += __shfl_xor_sync(0xffffffffu, s,  o);
            s2 += __shfl_xor_sync(0xffffffffu, s2, o);
        }
        if (lane == 0) { red[0] = s; red[1] = s2; }
    }
    __syncthreads();
    float mean = red[0] * (1.f / DIMX);
    float var  = red[1] * (1.f / DIMX) - mean * mean;
    float inv  = rsqrtf(var + 1e-5f);
    for (int c = threadIdx.x; c < DIMX; c += blockDim.x) {
        float y = (xr[c] - mean) * inv * gam[c] + bet[c];
        fp16 h, l; split2h(y, h, l);
        oh[(size_t)row * DIMX + c] = h;
        ol[(size_t)row * DIMX + c] = l;
    }
}

// ---------------- transpose fp32 -> single fp16 ----------------
__global__ void tsingle_kernel(const float* __restrict__ in, int ldin, long long sIn,
                               fp16* __restrict__ o, int ldout, long long sOut,
                               int R, int C)
{
    __shared__ float t[32][33];
    in += (size_t)blockIdx.z * sIn;
    o  += (size_t)blockIdx.z * sOut;
    int r0 = blockIdx.y * 32, c0 = blockIdx.x * 32;
    int tx = threadIdx.x & 31, ty = threadIdx.x >> 5;
#pragma unroll
    for (int i = 0; i < 32; i += 8) {
        int r = r0 + ty + i;
        if (r < R && c0 + tx < C) t[ty + i][tx] = in[(size_t)r * ldin + c0 + tx];
    }
    __syncthreads();
#pragma unroll
    for (int i = 0; i < 32; i += 8) {
        int c = c0 + ty + i, r = r0 + tx;
        if (c < C && r < R)
            o[(size_t)c * ldout + r] = __float2half_rn(t[tx][ty + i]);
    }
}

// ---------------- transpose fp16 -> fp16 ----------------
__global__ void t16_kernel(const fp16* __restrict__ in, int ldin, long long sIn,
                           fp16* __restrict__ o, int ldout, long long sOut,
                           int R, int C)
{
    __shared__ fp16 t[32][34];
    in += (size_t)blockIdx.z * sIn;
    o  += (size_t)blockIdx.z * sOut;
    int r0 = blockIdx.y * 32, c0 = blockIdx.x * 32;
    int tx = threadIdx.x & 31, ty = threadIdx.x >> 5;
#pragma unroll
    for (int i = 0; i < 32; i += 8) {
        int r = r0 + ty + i;
        if (r < R && c0 + tx < C) t[ty + i][tx] = in[(size_t)r * ldin + c0 + tx];
    }
    __syncthreads();
#pragma unroll
    for (int i = 0; i < 32; i += 8) {
        int c = c0 + ty + i, r = r0 + tx;
        if (c < C && r < R)
            o[(size_t)c * ldout + r] = t[tx][ty + i];
    }
}

// ---------------- fp16 tensor-core GEMM ----------------
// C = alpha * A @ B^T.  128 threads, warp grid (BM/WM) x (BN/WN) = 4 warps.
// ASPLIT: A hi/lo (adds al*b MMA). OCC: min CTAs/SM for launch_bounds.
// MODE 0: C fp32 (+bias). MODE 1: C single fp16 (Ch). MODE 2: blend with Hm.
// MODE 4: fused QK remap: col<1024 -> q split to Ch/Cl at [h][i][d];
//         else -> k single to Ck at [h][i][d]. (warp-uniform branch: WN=64)
template<int BM, int BN, int WM, int WN, int ASPLIT, int MODE, int OCC>
__global__ void __launch_bounds__(128, OCC)
gemm_f16(const fp16* __restrict__ Ahi, const fp16* __restrict__ Alo,
         const fp16* __restrict__ Bhi,
         float* __restrict__ C, fp16* __restrict__ Ch, fp16* __restrict__ Cl,
         fp16* __restrict__ Ck,
         const float* __restrict__ Hm,
         int K, int lda, int ldb, int ldc,
         long long sA, long long sB, long long sC,
         float alpha, const float* __restrict__ bias)
{
    constexpr int MI  = WM / 16;
    constexpr int NJ  = WN / 16;
    constexpr int NJ2 = WN / 8;
    constexpr int NAI = BM / 16;
    constexpr int NBI = BN / 16;
    constexpr int ABUF = (ASPLIT ? 2 : 1) * BM * 64;  // halves
    constexpr int BBUF = BN * 64;
    constexpr int SS   = ABUF + BBUF;
    constexpr int WNN = BN / WN;

    extern __shared__ fp16 sm[];

    Ahi += (size_t)blockIdx.z * sA;
    if (ASPLIT) Alo += (size_t)blockIdx.z * sA;
    Bhi += (size_t)blockIdx.z * sB;
    if (MODE == 1) Ch += (size_t)blockIdx.z * sC;
    else if (MODE != 4) C += (size_t)blockIdx.z * sC;
    if (MODE == 2) Hm += (size_t)blockIdx.z * sC;

    const int bm = blockIdx.y * BM, bn = blockIdx.x * BN;
    const int tid = threadIdx.x, lane = tid & 31, wid = tid >> 5;
    const int wm0 = (wid / WNN) * WM, wn0 = (wid % WNN) * WN;

    float acc[MI][NJ2][4];
#pragma unroll
    for (int i = 0; i < MI; i++)
#pragma unroll
        for (int j = 0; j < NJ2; j++) {
            acc[i][j][0] = 0.f; acc[i][j][1] = 0.f;
            acc[i][j][2] = 0.f; acc[i][j][3] = 0.f;
        }

    auto issue = [&](int kt, int stg) {
        fp16* sA_hi = sm + stg * SS;
        fp16* sA_lo = sA_hi + BM * 64;
        fp16* sB_hi = sA_hi + ABUF;
#pragma unroll
        for (int i = 0; i < NAI; i++) {
            int id = tid + i * 128, r = id >> 3, c = id & 7;
            size_t go = (size_t)(bm + r) * lda + kt * 64 + c * 8;
            int so = r * 64 + ((c ^ (r & 7)) << 3);
            cp16(s2u(sA_hi + so), Ahi + go);
            if (ASPLIT) cp16(s2u(sA_lo + so), Alo + go);
        }
#pragma unroll
        for (int i = 0; i < NBI; i++) {
            int id = tid + i * 128, r = id >> 3, c = id & 7;
            size_t go = (size_t)(bn + r) * ldb + kt * 64 + c * 8;
            int so = r * 64 + ((c ^ (r & 7)) << 3);
            cp16(s2u(sB_hi + so), Bhi + go);
        }
    };

    const int KT = K >> 6;
    issue(0, 0); cpcommit();

    for (int kt = 0; kt < KT; kt++) {
        int cur = kt & 1;
        if (kt + 1 < KT) { issue(kt + 1, cur ^ 1); cpcommit(); cpwait<1>(); }
        else             { cpwait<0>(); }
        __syncthreads();

        const fp16* sA_hi = sm + cur * SS;
        const fp16* sA_lo = sA_hi + BM * 64;
        const fp16* sB_hi = sA_hi + ABUF;

#pragma unroll
        for (int s = 0; s < 4; s++) {
            const int c0 = 2 * s;
            uint32_t ah[MI][4], al[MI][4];
#pragma unroll
            for (int mi = 0; mi < MI; mi++) {
                int row = wm0 + mi * 16 + (lane & 15);
                int ch  = c0 + (lane >> 4);
                int off = row * 64 + ((ch ^ (row & 7)) << 3);
                ldsm4(ah[mi], s2u(sA_hi + off));
                if (ASPLIT) ldsm4(al[mi], s2u(sA_lo + off));
            }
#pragma unroll
            for (int nj = 0; nj < NJ; nj++) {
                int rowb = wn0 + nj * 16 + (lane & 15);
                int ch   = c0 + (lane >> 4);
                int off  = rowb * 64 + ((ch ^ (rowb & 7)) << 3);
                uint32_t bb[4];
                ldsm4(bb, s2u(sB_hi + off));
#pragma unroll
                for (int mi = 0; mi < MI; mi++) {
                    mma_f16(acc[mi][2 * nj],     ah[mi], bb[0], bb[2]);
                    mma_f16(acc[mi][2 * nj + 1], ah[mi], bb[1], bb[3]);
                    if (ASPLIT) {
                        mma_f16(acc[mi][2 * nj],     al[mi], bb[0], bb[2]);
                        mma_f16(acc[mi][2 * nj + 1], al[mi], bb[1], bb[3]);
                    }
                }
            }
        }
        __syncthreads();
    }

    // ---- epilogue ----
#pragma unroll
    for (int mi = 0; mi < MI; mi++) {
#pragma unroll
        for (int nj2 = 0; nj2 < NJ2; nj2++) {
            int r0  = bm + wm0 + mi * 16 + (lane >> 2);
            int col = bn + wn0 + nj2 * 8 + (lane & 3) * 2;
            float v0 = acc[mi][nj2][0] * alpha, v1 = acc[mi][nj2][1] * alpha;
            float v2 = acc[mi][nj2][2] * alpha, v3 = acc[mi][nj2][3] * alpha;
            if (MODE == 4) {
                if (col < INNER) {
                    int h = col >> 6, d = col & 63;
                    size_t dst = ((size_t)h * N_TOK + r0) * DHEAD + d;
                    fp16 a0, b0, a1, b1;
                    split2h(v0, a0, b0); split2h(v1, a1, b1);
                    *(__half2*)&Ch[dst] = __halves2half2(a0, a1);
                    *(__half2*)&Cl[dst] = __halves2half2(b0, b1);
                    split2h(v2, a0, b0); split2h(v3, a1, b1);
                    *(__half2*)&Ch[dst + 8 * DHEAD] = __halves2half2(a0, a1);
                    *(__half2*)&Cl[dst + 8 * DHEAD] = __halves2half2(b0, b1);
                } else {
                    int h = (col - INNER) >> 6, d = col & 63;
                    size_t dst = ((size_t)h * N_TOK + r0) * DHEAD + d;
                    *(__half2*)&Ck[dst] =
                        __halves2half2(__float2half_rn(v0), __float2half_rn(v1));
                    *(__half2*)&Ck[dst + 8 * DHEAD] =
                        __halves2half2(__float2half_rn(v2), __float2half_rn(v3));
                }
                continue;
            }
            size_t o0 = (size_t)r0 * ldc + col;
            size_t o1 = o0 + (size_t)8 * ldc;
            if (MODE == 1) {
                *(__half2*)&Ch[o0] = __halves2half2(__float2half_rn(v0), __float2half_rn(v1));
                *(__half2*)&Ch[o1] = __halves2half2(__float2half_rn(v2), __float2half_rn(v3));
            } else if (MODE == 2) {
                float2 ha = *(const float2*)&Hm[o0];
                float2 hb = *(const float2*)&Hm[o1];
                *(float2*)&C[o0] = make_float2(ALPHA_C * v0 + (1.f - ALPHA_C) * ha.x,
                                               ALPHA_C * v1 + (1.f - ALPHA_C) * ha.y);
                *(float2*)&C[o1] = make_float2(ALPHA_C * v2 + (1.f - ALPHA_C) * hb.x,
                                               ALPHA_C * v3 + (1.f - ALPHA_C) * hb.y);
            } else {
                if (bias) {
                    float b0 = bias[col], b1 = bias[col + 1];
                    v0 += b0; v1 += b1; v2 += b0; v3 += b1;
                }
                *(float2*)&C[o0] = make_float2(v0, v1);
                *(float2*)&C[o1] = make_float2(v2, v3);
            }
        }
    }
}

// ---------------- fused mix_pre + softmax + mix_post ----------------
__global__ void __launch_bounds__(512)
fused_softmax(const float* __restrict__ blended,
              const float* __restrict__ mpre, const float* __restrict__ mpost,
              fp16* __restrict__ at)
{
    extern __shared__ float sd[];                        // [16][2048] mixed dots
    float* redM = sd + HEADS * N_TOK;                    // [16][512]
    float* redL = redM + HEADS * 512;                    // [16][512]
    __shared__ float smixA[HEADS * HEADS];
    __shared__ __half2 smixB2[HEADS * HEADS];
    __shared__ float fm[HEADS], fl[HEADS];

    const int i = blockIdx.x, tid = threadIdx.x;
    const int warp = tid >> 5, lane = tid & 31;
    if (tid < 256) {
        smixA[tid] = mpre[tid];
        smixB2[tid] = __half2half2(__float2half_rn(mpost[tid]));
    }
    __syncthreads();

    const size_t sH = (size_t)N_TOK * N_TOK;
    const size_t hbase = (size_t)i * N_TOK;
    const int j = tid * 4;

    float4 bl4[HEADS];
#pragma unroll
    for (int h = 0; h < HEADS; h++)
        bl4[h] = *(const float4*)&blended[(size_t)h * sH + hbase + j];

    float m[HEADS], l[HEADS];
#pragma unroll
    for (int g = 0; g < HEADS; g++) {
        float4 d = make_float4(0.f, 0.f, 0.f, 0.f);
#pragma unroll
        for (int h = 0; h < HEADS; h++) {
            float w = smixA[h * HEADS + g];
            d.x += bl4[h].x * w; d.y += bl4[h].y * w;
            d.z += bl4[h].z * w; d.w += bl4[h].w * w;
        }
        *(float4*)&sd[g * N_TOK + j] = d;
        float mx = fmaxf(fmaxf(d.x, d.y), fmaxf(d.z, d.w));
        m[g] = mx;
        l[g] = __expf(d.x - mx) + __expf(d.y - mx)
             + __expf(d.z - mx) + __expf(d.w - mx);
    }

#pragma unroll
    for (int g = 0; g < HEADS; g++) { redM[g * 512 + tid] = m[g]; redL[g * 512 + tid] = l[g]; }
    __syncthreads();
    {
        int g = warp;
        float M = redM[g * 512 + lane], L = redL[g * 512 + lane];
#pragma unroll
        for (int r = 1; r < 16; r++) {
            float m2 = redM[g * 512 + lane + r * 32];
            float l2 = redL[g * 512 + lane + r * 32];
            float nm = fmaxf(M, m2);
            L = L * __expf(M - nm) + l2 * __expf(m2 - nm);
            M = nm;
        }
        for (int o = 16; o > 0; o >>= 1) {
            float m2 = __shfl_xor_sync(0xffffffffu, M, o);
            float l2 = __shfl_xor_sync(0xffffffffu, L, o);
            float nm = fmaxf(M, m2);
            L = L * __expf(M - nm) + l2 * __expf(m2 - nm);
            M = nm;
        }
        if (lane == 0) { fm[g] = M; fl[g] = 1.0f / L; }
    }
    __syncthreads();

    __half2 p01[HEADS], p23[HEADS];
#pragma unroll
    for (int h = 0; h < HEADS; h++) {
        float mh = fm[h], li = fl[h];
        float4 d = *(const float4*)&sd[h * N_TOK + j];
        p01[h] = __floats2half2_rn(__expf(d.x - mh) * li, __expf(d.y - mh) * li);
        p23[h] = __floats2half2_rn(__expf(d.z - mh) * li, __expf(d.w - mh) * li);
    }
    const size_t rbase = (size_t)i * (HEADS * N_TOK);
#pragma unroll
    for (int g = 0; g < HEADS; g++) {
        __half2 a01 = __float2half2_rn(0.f), a23 = __float2half2_rn(0.f);
#pragma unroll
        for (int h = 0; h < HEADS; h++) {
            __half2 w2 = smixB2[h * HEADS + g];
            a01 = __hfma2(p01[h], w2, a01);
            a23 = __hfma2(p23[h], w2, a23);
        }
        size_t o = rbase + g * N_TOK + j;
        ((__half2*)&at[o])[0] = a01;
        ((__half2*)&at[o])[1] = a23;
    }
}

// ---------------- launch ----------------
extern "C" void kernel_launch(void* const* d_in, const int* in_sizes, int n_in,
                              void* d_out, int out_size)
{
    const float* x        = (const float*)d_in[0];
    const float* h_in     = (const float*)d_in[1];
    const float* ln_g     = (const float*)d_in[2];
    const float* ln_b     = (const float*)d_in[3];
    const float* Wq       = (const float*)d_in[4];
    const float* Wkv      = (const float*)d_in[5];
    const float* mix_pre  = (const float*)d_in[6];
    const float* mix_post = (const float*)d_in[7];
    const float* Wout     = (const float*)d_in[8];
    const float* bout     = (const float*)d_in[9];

    float* out = (float*)d_out;
    float* blended_out = out + (size_t)N_TOK * DIMX;

    fp16 *v16, *xnh, *xnl, *wqkv, *wo, *qh, *ql, *k, *vt, *at, *ao;
    cudaGetSymbolAddress((void**)&v16,  g_v16);
    cudaGetSymbolAddress((void**)&xnh,  g_xnh);
    cudaGetSymbolAddress((void**)&xnl,  g_xnl);
    cudaGetSymbolAddress((void**)&wqkv, g_wqkv);
    cudaGetSymbolAddress((void**)&wo,   g_wo);
    cudaGetSymbolAddress((void**)&qh,   g_qh);
    cudaGetSymbolAddress((void**)&ql,   g_ql);
    cudaGetSymbolAddress((void**)&k,    g_k);
    cudaGetSymbolAddress((void**)&vt,   g_vt);
    cudaGetSymbolAddress((void**)&at,   g_at);
    cudaGetSymbolAddress((void**)&ao,   g_ao);

    // smem sizes (bytes)
    const int SM_QKV = 2 * (2 * 128 + 128) * 128;   // 98304 (A split, 2 stg)
    const int SM_QK  = (2 * 128 + 64) * 128;        // 40960 (A split, BN=64, 1 stg)
    const int SM_AV  = 2 * (128 + 64) * 128;        // 49152 (no split, 2 stg)
    const int SM_SOFT = HEADS * N_TOK * 4 + 2 * HEADS * 512 * 4;  // 196608
    cudaFuncSetAttribute(gemm_f16<128, 128, 64, 64, 1, 4, 2>,
                         cudaFuncAttributeMaxDynamicSharedMemorySize, SM_QKV);
    cudaFuncSetAttribute(gemm_f16<128, 64, 64, 32, 1, 2, 3>,
                         cudaFuncAttributeMaxDynamicSharedMemorySize, SM_QK);
    cudaFuncSetAttribute(gemm_f16<128, 64, 64, 32, 0, 1, 2>,
                         cudaFuncAttributeMaxDynamicSharedMemorySize, SM_AV);
    cudaFuncSetAttribute(gemm_f16<128, 64, 64, 32, 0, 0, 2>,
                         cudaFuncAttributeMaxDynamicSharedMemorySize, SM_AV);
    cudaFuncSetAttribute(fused_softmax,
                         cudaFuncAttributeMaxDynamicSharedMemorySize, SM_SOFT);

    // 1. layernorm + fp16 split
    ln_split_kernel<<<N_TOK, 256>>>(x, ln_g, ln_b, xnh, xnl);

    // 2. weight transposes -> single fp16 K-major
    tsingle_kernel<<<dim3(32, 32, 1), 256>>>(Wq, INNER, 0, wqkv, DIMX, 0, DIMX, INNER);
    tsingle_kernel<<<dim3(64, 32, 1), 256>>>(Wkv, 2 * INNER, 0,
                                             wqkv + (size_t)INNER * DIMX, DIMX, 0,
                                             DIMX, 2 * INNER);
    tsingle_kernel<<<dim3(32, 32, 1), 256>>>(Wout, DIMX, 0, wo, INNER, 0, INNER, DIMX);

    // 3a. q/k gemm with FUSED remap epilogue: q -> qh/ql [h][i][d], k -> k
    gemm_f16<128, 128, 64, 64, 1, 4, 2><<<dim3(2 * INNER / 128, N_TOK / 128, 1), 128, SM_QKV>>>(
        xnh, xnl, wqkv, nullptr, qh, ql, k, nullptr,
        DIMX, DIMX, DIMX, 0, 0, 0, 0, 1.f, nullptr);

    // 3b. v16 = xnh @ Wv  (M=2048, N=1024, K=1024)  1-MMA -> fp16 direct
    gemm_f16<128, 64, 64, 32, 0, 1, 2><<<dim3(INNER / 64, N_TOK / 128, 1), 128, SM_AV>>>(
        xnh, nullptr, wqkv + (size_t)(2 * INNER) * DIMX, nullptr, v16, nullptr, nullptr, nullptr,
        DIMX, DIMX, DIMX, INNER, 0, 0, 0, 1.f, nullptr);

    // 4. v^T (fp16 -> fp16 transpose)
    t16_kernel<<<dim3(2, 64, HEADS), 256>>>(v16, INNER, DHEAD,
                                            vt, N_TOK, (long long)DHEAD * N_TOK,
                                            N_TOK, DHEAD);

    // 5. blended[h][i][j] = 0.45*SCALE*(q@k^T) + 0.55*h  (BN=64, 3 CTAs/SM)
    gemm_f16<128, 64, 64, 32, 1, 2, 3><<<dim3(N_TOK / 64, N_TOK / 128, HEADS), 128, SM_QK>>>(
        qh, ql, k, blended_out, nullptr, nullptr, nullptr, h_in,
        DHEAD, DHEAD, DHEAD, N_TOK,
        (long long)N_TOK * DHEAD, (long long)N_TOK * DHEAD,
        (long long)N_TOK * N_TOK,
        SCALE_C, nullptr);

    // 6. fused mix_pre + softmax + mix_post -> attn single fp16 [i][g][j]
    fused_softmax<<<N_TOK, 512, SM_SOFT>>>(blended_out, mix_pre, mix_post, at);

    // 7. ao = attn @ v  (per head; M=2048, N=64, K=2048) 1-MMA -> single fp16
    gemm_f16<128, 64, 64, 32, 0, 1, 2><<<dim3(1, N_TOK / 128, HEADS), 128, SM_AV>>>(
        at, nullptr, vt, nullptr, ao, nullptr, nullptr, nullptr,
        N_TOK, HEADS * N_TOK, N_TOK, INNER,
        (long long)N_TOK, (long long)DHEAD * N_TOK, (long long)DHEAD,
        1.f, nullptr);

    // 8. out = ao @ Wout + bout  (M=2048, N=1024, K=1024) 1-MMA, BN=64
    gemm_f16<128, 64, 64, 32, 0, 0, 2><<<dim3(DIMX / 64, N_TOK / 128, 1), 128, SM_AV>>>(
        ao, nullptr, wo, out, nullptr, nullptr, nullptr, nullptr,
        INNER, INNER, INNER, DIMX, 0, 0, 0, 1.f, bout);

    (void)in_sizes; (void)n_in; (void)out_size;
}